// round 5
// baseline (speedup 1.0000x reference)
#include <cuda_runtime.h>
#include <cuda_bf16.h>
#include <cstdint>

#define BB 4
#define NN 2048
#define KC 2048
#define DD 1024
#define HH 16
#define HD 64
#define RMS_EPS 1e-6f

// ---------------------------------------------------------------------------
// Scratch (bf16 hi/lo split arrays)
// ---------------------------------------------------------------------------
__device__ __nv_bfloat16 g_x_hi[BB*NN*DD],   g_x_lo[BB*NN*DD];
__device__ __nv_bfloat16 g_qw_hi[DD*DD],     g_qw_lo[DD*DD];
__device__ __nv_bfloat16 g_kvw_hi[DD*2*DD],  g_kvw_lo[DD*2*DD];
__device__ __nv_bfloat16 g_pw_hi[DD*DD],     g_pw_lo[DD*DD];
__device__ __nv_bfloat16 g_cn_hi[BB*KC*DD],  g_cn_lo[BB*KC*DD];
__device__ __nv_bfloat16 g_q_hi[BB*NN*DD],   g_q_lo[BB*NN*DD];      // pre-scaled 0.125
__device__ __nv_bfloat16 g_kv_hi[BB*KC*2*DD],g_kv_lo[BB*KC*2*DD];
__device__ __nv_bfloat16 g_ao_hi[BB*NN*DD],  g_ao_lo[BB*NN*DD];

// ---------------------------------------------------------------------------
// PTX helpers
// ---------------------------------------------------------------------------
__device__ __forceinline__ uint32_t smem_u32(const void* p) {
    return (uint32_t)__cvta_generic_to_shared(p);
}
__device__ __forceinline__ void ldsm4(uint32_t a, uint32_t& r0, uint32_t& r1,
                                      uint32_t& r2, uint32_t& r3) {
    asm volatile("ldmatrix.sync.aligned.m8n8.x4.shared.b16 {%0,%1,%2,%3}, [%4];"
                 : "=r"(r0), "=r"(r1), "=r"(r2), "=r"(r3) : "r"(a));
}
__device__ __forceinline__ void ldsm4t(uint32_t a, uint32_t& r0, uint32_t& r1,
                                       uint32_t& r2, uint32_t& r3) {
    asm volatile("ldmatrix.sync.aligned.m8n8.x4.trans.shared.b16 {%0,%1,%2,%3}, [%4];"
                 : "=r"(r0), "=r"(r1), "=r"(r2), "=r"(r3) : "r"(a));
}
__device__ __forceinline__ void mma_bf16(float* c, const uint32_t* a, const uint32_t* b) {
    asm volatile(
        "mma.sync.aligned.m16n8k16.row.col.f32.bf16.bf16.f32 "
        "{%0,%1,%2,%3},{%4,%5,%6,%7},{%8,%9},{%0,%1,%2,%3};\n"
        : "+f"(c[0]), "+f"(c[1]), "+f"(c[2]), "+f"(c[3])
        : "r"(a[0]), "r"(a[1]), "r"(a[2]), "r"(a[3]), "r"(b[0]), "r"(b[1]));
}
__device__ __forceinline__ void cpa16(void* dst, const void* src) {
    uint32_t d = smem_u32(dst);
    asm volatile("cp.async.cg.shared.global [%0], [%1], 16;\n" :: "r"(d), "l"(src));
}
__device__ __forceinline__ void split2(float v, __nv_bfloat16& h, __nv_bfloat16& l) {
    h = __float2bfloat16(v);
    l = __float2bfloat16(v - __bfloat162float(h));
}

// ---------------------------------------------------------------------------
// fp32 -> bf16 hi/lo split
// ---------------------------------------------------------------------------
__global__ __launch_bounds__(256) void split_kernel(const float* __restrict__ src,
                                                    __nv_bfloat16* __restrict__ hi,
                                                    __nv_bfloat16* __restrict__ lo, int n)
{
    int i = (blockIdx.x * 256 + threadIdx.x) * 4;
    if (i >= n) return;
    float4 v = *reinterpret_cast<const float4*>(src + i);
    __nv_bfloat16 h0,l0,h1,l1,h2,l2,h3,l3;
    split2(v.x,h0,l0); split2(v.y,h1,l1); split2(v.z,h2,l2); split2(v.w,h3,l3);
    hi[i]=h0; hi[i+1]=h1; hi[i+2]=h2; hi[i+3]=h3;
    lo[i]=l0; lo[i+1]=l1; lo[i+2]=l2; lo[i+3]=l3;
}

// ---------------------------------------------------------------------------
// RMSNorm -> bf16 hi/lo
// ---------------------------------------------------------------------------
__global__ __launch_bounds__(256) void rmsnorm_split(const float* __restrict__ ctx)
{
    const int row = blockIdx.x;
    float4 v = reinterpret_cast<const float4*>(ctx + (size_t)row * DD)[threadIdx.x];
    float s = v.x*v.x + v.y*v.y + v.z*v.z + v.w*v.w;
    #pragma unroll
    for (int o = 16; o > 0; o >>= 1) s += __shfl_xor_sync(0xffffffffu, s, o);
    __shared__ float ws[8];
    if ((threadIdx.x & 31) == 0) ws[threadIdx.x >> 5] = s;
    __syncthreads();
    float tot = 0.f;
    #pragma unroll
    for (int i = 0; i < 8; i++) tot += ws[i];
    const float r = rsqrtf(tot * (1.0f / (float)DD) + RMS_EPS);
    const size_t base = (size_t)row * DD + threadIdx.x * 4;
    __nv_bfloat16 h, l;
    split2(v.x*r,h,l); g_cn_hi[base+0]=h; g_cn_lo[base+0]=l;
    split2(v.y*r,h,l); g_cn_hi[base+1]=h; g_cn_lo[base+1]=l;
    split2(v.z*r,h,l); g_cn_hi[base+2]=h; g_cn_lo[base+2]=l;
    split2(v.w*r,h,l); g_cn_hi[base+3]=h; g_cn_lo[base+3]=l;
}

// ---------------------------------------------------------------------------
// Split-bf16 GEMM (validated R3): C = (Ahi+Alo)@(Whi+Wlo) + bias
// tile 128x128x32, 256 threads, double-buffered cp.async.
// ---------------------------------------------------------------------------
#define GBM 128
#define GBN 128
#define GBK 32
#define APAD 40
#define WPAD 136
#define A_EL (GBM*APAD)
#define W_EL (GBK*WPAD)
#define STG_EL (2*A_EL + 2*W_EL)
#define GEMM_SMEM (2*STG_EL*2)

template<bool SPLIT>
__global__ __launch_bounds__(256, 1) void mmgemm(
    const __nv_bfloat16* __restrict__ Ahi, const __nv_bfloat16* __restrict__ Alo,
    const __nv_bfloat16* __restrict__ Whi, const __nv_bfloat16* __restrict__ Wlo,
    const float* __restrict__ bias, float scale,
    float* __restrict__ Cf, __nv_bfloat16* __restrict__ Chi, __nv_bfloat16* __restrict__ Clo,
    int M, int N, int K)
{
    extern __shared__ __nv_bfloat16 sm[];
    const int tid = threadIdx.x;
    const int wid = tid >> 5, lane = tid & 31;
    const int rowBase = blockIdx.y * GBM;
    const int colBase = blockIdx.x * GBN;
    const int wm = wid & 3;
    const int wn = wid >> 2;

    auto loadStage = [&](int kc, int s) {
        const int k0 = kc * GBK;
        __nv_bfloat16* Ah = sm + s * STG_EL;
        __nv_bfloat16* Al = Ah + A_EL;
        __nv_bfloat16* Wh = Al + A_EL;
        __nv_bfloat16* Wl = Wh + W_EL;
        #pragma unroll
        for (int i = 0; i < 2; i++) {
            int t = tid + i * 256;
            int r = t >> 2, ch = t & 3;
            size_t ga = (size_t)(rowBase + r) * K + k0 + ch * 8;
            cpa16(Ah + r * APAD + ch * 8, Ahi + ga);
            cpa16(Al + r * APAD + ch * 8, Alo + ga);
            int rw = t >> 4, cw = t & 15;
            size_t gw = (size_t)(k0 + rw) * N + colBase + cw * 8;
            cpa16(Wh + rw * WPAD + cw * 8, Whi + gw);
            cpa16(Wl + rw * WPAD + cw * 8, Wlo + gw);
        }
        asm volatile("cp.async.commit_group;\n");
    };

    float acc[2][8][4];
    #pragma unroll
    for (int mt = 0; mt < 2; mt++)
        #pragma unroll
        for (int nt = 0; nt < 8; nt++)
            #pragma unroll
            for (int e = 0; e < 4; e++) acc[mt][nt][e] = 0.f;

    const int NK = K / GBK;
    loadStage(0, 0);
    for (int kc = 0; kc < NK; kc++) {
        if (kc + 1 < NK) {
            loadStage(kc + 1, (kc + 1) & 1);
            asm volatile("cp.async.wait_group 1;\n");
        } else {
            asm volatile("cp.async.wait_group 0;\n");
        }
        __syncthreads();

        __nv_bfloat16* Ah = sm + (kc & 1) * STG_EL;
        __nv_bfloat16* Al = Ah + A_EL;
        __nv_bfloat16* Wh = Al + A_EL;
        __nv_bfloat16* Wl = Wh + W_EL;

        #pragma unroll
        for (int k16 = 0; k16 < 2; k16++) {
            const int kk = k16 * 16;
            uint32_t ah[2][4], al[2][4];
            #pragma unroll
            for (int mt = 0; mt < 2; mt++) {
                int r = wm * 32 + mt * 16 + (lane & 7) + ((lane >> 3) & 1) * 8;
                int c = kk + (lane >> 4) * 8;
                ldsm4(smem_u32(Ah + r * APAD + c), ah[mt][0], ah[mt][1], ah[mt][2], ah[mt][3]);
                ldsm4(smem_u32(Al + r * APAD + c), al[mt][0], al[mt][1], al[mt][2], al[mt][3]);
            }
            uint32_t bh[8][2], bl[8][2];
            #pragma unroll
            for (int np = 0; np < 4; np++) {
                int r = kk + (lane & 7) + ((lane >> 3) & 1) * 8;
                int c = wn * 64 + np * 16 + (lane >> 4) * 8;
                uint32_t r0, r1, r2, r3;
                ldsm4t(smem_u32(Wh + r * WPAD + c), r0, r1, r2, r3);
                bh[2*np][0]=r0; bh[2*np][1]=r1; bh[2*np+1][0]=r2; bh[2*np+1][1]=r3;
                ldsm4t(smem_u32(Wl + r * WPAD + c), r0, r1, r2, r3);
                bl[2*np][0]=r0; bl[2*np][1]=r1; bl[2*np+1][0]=r2; bl[2*np+1][1]=r3;
            }
            #pragma unroll
            for (int mt = 0; mt < 2; mt++)
                #pragma unroll
                for (int nt = 0; nt < 8; nt++) {
                    mma_bf16(acc[mt][nt], ah[mt], bh[nt]);
                    mma_bf16(acc[mt][nt], ah[mt], bl[nt]);
                    mma_bf16(acc[mt][nt], al[mt], bh[nt]);
                }
        }
        __syncthreads();
    }

    #pragma unroll
    for (int mt = 0; mt < 2; mt++)
        #pragma unroll
        for (int nt = 0; nt < 8; nt++) {
            int row = rowBase + wm * 32 + mt * 16 + (lane >> 2);
            int col = colBase + wn * 64 + nt * 8 + 2 * (lane & 3);
            float b0 = bias[col], b1 = bias[col + 1];
            float v00 = (acc[mt][nt][0] + b0) * scale;
            float v01 = (acc[mt][nt][1] + b1) * scale;
            float v10 = (acc[mt][nt][2] + b0) * scale;
            float v11 = (acc[mt][nt][3] + b1) * scale;
            size_t i0 = (size_t)row * N + col;
            size_t i1 = (size_t)(row + 8) * N + col;
            if (SPLIT) {
                __nv_bfloat16 h, l;
                split2(v00, h, l); Chi[i0]     = h; Clo[i0]     = l;
                split2(v01, h, l); Chi[i0 + 1] = h; Clo[i0 + 1] = l;
                split2(v10, h, l); Chi[i1]     = h; Clo[i1]     = l;
                split2(v11, h, l); Chi[i1 + 1] = h; Clo[i1 + 1] = l;
            } else {
                Cf[i0] = v00; Cf[i0 + 1] = v01;
                Cf[i1] = v10; Cf[i1 + 1] = v11;
            }
        }
}

// ---------------------------------------------------------------------------
// Attention, split-bf16 mma.sync, 2-stage cp.async double-buffered K/V.
// Block = (b,h, 128 q-rows); 8 warps; kc tiles of 64.
// smem: Qh/Ql 128x72, 2 stages of (Kh,Kl,Vh,Vl) 64x72, Ph/Pl 128x72, dsum
// ---------------------------------------------------------------------------
#define ANT 128
#define AKT 64
#define APITCH 72
#define Q_EL (ANT*APITCH)            // 9216
#define KV_ARR (AKT*APITCH)          // 4608
#define KV_STAGE (4*KV_ARR)          // 18432
#define ATTN_SMEM ((2*Q_EL + 2*KV_STAGE + 2*Q_EL) * 2 + ANT * 4)

__global__ __launch_bounds__(256, 1) void attn_mma()
{
    extern __shared__ __nv_bfloat16 smb[];
    __nv_bfloat16* Qh = smb;
    __nv_bfloat16* Ql = Qh + Q_EL;
    __nv_bfloat16* KV = Ql + Q_EL;          // stage s at KV + s*KV_STAGE
    __nv_bfloat16* Ph = KV + 2*KV_STAGE;
    __nv_bfloat16* Pl = Ph + Q_EL;
    float* dsum = (float*)(Pl + Q_EL);

    const int tid = threadIdx.x, wid = tid >> 5, lane = tid & 31;
    const int b = blockIdx.x >> 4, h = blockIdx.x & 15;
    const int n0 = blockIdx.y * ANT;

    auto loadKV = [&](int kc0, int s) {
        __nv_bfloat16* base = KV + s * KV_STAGE;
        #pragma unroll
        for (int i = 0; i < 2; i++) {
            int t = tid + i * 256;
            int r = t >> 3, ch = t & 7;
            size_t gk = (size_t)(b * KC + kc0 + r) * (2 * DD) + h * HD + ch * 8;
            cpa16(base +            r * APITCH + ch * 8, g_kv_hi + gk);
            cpa16(base + KV_ARR   + r * APITCH + ch * 8, g_kv_lo + gk);
            cpa16(base + 2*KV_ARR + r * APITCH + ch * 8, g_kv_hi + gk + DD);
            cpa16(base + 3*KV_ARR + r * APITCH + ch * 8, g_kv_lo + gk + DD);
        }
        asm volatile("cp.async.commit_group;\n");
    };

    // Q via cp.async (folded into group 0 with first KV tile)
    #pragma unroll
    for (int i = 0; i < 4; i++) {
        int t = tid + i * 256;
        int r = t >> 3, ch = t & 7;
        size_t g = (size_t)(b * NN + n0 + r) * DD + h * HD + ch * 8;
        cpa16(Qh + r * APITCH + ch * 8, g_q_hi + g);
        cpa16(Ql + r * APITCH + ch * 8, g_q_lo + g);
    }
    if (tid < ANT) dsum[tid] = 0.f;
    loadKV(0, 0);        // group 0 (Q + KV tile 0)
    loadKV(AKT, 1);      // group 1

    float oacc[8][4];
    #pragma unroll
    for (int nt = 0; nt < 8; nt++)
        #pragma unroll
        for (int e = 0; e < 4; e++) oacc[nt][e] = 0.f;

    const int NIT = KC / AKT;   // 32
    for (int it = 0; it < NIT; it++) {
        const int s = it & 1;
        __nv_bfloat16* Kh = KV + s * KV_STAGE;
        __nv_bfloat16* Kl = Kh + KV_ARR;
        __nv_bfloat16* Vh = Kh + 2*KV_ARR;
        __nv_bfloat16* Vl = Kh + 3*KV_ARR;

        if (it + 1 < NIT) asm volatile("cp.async.wait_group 1;\n");
        else              asm volatile("cp.async.wait_group 0;\n");
        __syncthreads();   // (A) tile s data visible to all warps

        // S = Q @ K^T
        float sacc[8][4];
        #pragma unroll
        for (int nt = 0; nt < 8; nt++)
            #pragma unroll
            for (int e = 0; e < 4; e++) sacc[nt][e] = 0.f;

        #pragma unroll
        for (int d16 = 0; d16 < 4; d16++) {
            const int dd0 = d16 * 16;
            uint32_t ah[4], al[4];
            {
                int r = wid * 16 + (lane & 7) + ((lane >> 3) & 1) * 8;
                int c = dd0 + (lane >> 4) * 8;
                ldsm4(smem_u32(Qh + r * APITCH + c), ah[0], ah[1], ah[2], ah[3]);
                ldsm4(smem_u32(Ql + r * APITCH + c), al[0], al[1], al[2], al[3]);
            }
            uint32_t bh[8][2], bl[8][2];
            #pragma unroll
            for (int np = 0; np < 4; np++) {
                int r = np * 16 + (lane & 7) + ((lane >> 4)) * 8;
                int c = dd0 + ((lane >> 3) & 1) * 8;
                uint32_t r0, r1, r2, r3;
                ldsm4(smem_u32(Kh + r * APITCH + c), r0, r1, r2, r3);
                bh[2*np][0]=r0; bh[2*np][1]=r1; bh[2*np+1][0]=r2; bh[2*np+1][1]=r3;
                ldsm4(smem_u32(Kl + r * APITCH + c), r0, r1, r2, r3);
                bl[2*np][0]=r0; bl[2*np][1]=r1; bl[2*np+1][0]=r2; bl[2*np+1][1]=r3;
            }
            #pragma unroll
            for (int nt = 0; nt < 8; nt++) {
                mma_bf16(sacc[nt], ah, bh[nt]);
                mma_bf16(sacc[nt], ah, bl[nt]);
                mma_bf16(sacc[nt], al, bh[nt]);
            }
        }

        // P = exp(clip(S)) -> smem (split) + row sums
        float s0 = 0.f, s1 = 0.f;
        const int prow = wid * 16 + (lane >> 2);
        const int pcol0 = 2 * (lane & 3);
        #pragma unroll
        for (int nt = 0; nt < 8; nt++) {
            #pragma unroll
            for (int e = 0; e < 4; e++) {
                float v = __expf(fminf(fmaxf(sacc[nt][e], -10.f), 10.f));
                __nv_bfloat16 hb, lb;
                split2(v, hb, lb);
                int r = prow + ((e >> 1) ? 8 : 0);
                int c = nt * 8 + pcol0 + (e & 1);
                Ph[r * APITCH + c] = hb;
                Pl[r * APITCH + c] = lb;
                if (e >> 1) s1 += v; else s0 += v;
            }
        }
        s0 += __shfl_xor_sync(0xffffffffu, s0, 1);
        s0 += __shfl_xor_sync(0xffffffffu, s0, 2);
        s1 += __shfl_xor_sync(0xffffffffu, s1, 1);
        s1 += __shfl_xor_sync(0xffffffffu, s1, 2);
        if ((lane & 3) == 0) { dsum[prow] += s0; dsum[prow + 8] += s1; }
        __syncthreads();   // (B) all P written

        // O += P @ V
        #pragma unroll
        for (int k16 = 0; k16 < 4; k16++) {
            const int kk = k16 * 16;
            uint32_t ah[4], al[4];
            {
                int r = wid * 16 + (lane & 7) + ((lane >> 3) & 1) * 8;
                int c = kk + (lane >> 4) * 8;
                ldsm4(smem_u32(Ph + r * APITCH + c), ah[0], ah[1], ah[2], ah[3]);
                ldsm4(smem_u32(Pl + r * APITCH + c), al[0], al[1], al[2], al[3]);
            }
            uint32_t bh[8][2], bl[8][2];
            #pragma unroll
            for (int np = 0; np < 4; np++) {
                int rv = kk + (lane & 7) + ((lane >> 3) & 1) * 8;
                int cv = np * 16 + (lane >> 4) * 8;
                uint32_t r0, r1, r2, r3;
                ldsm4t(smem_u32(Vh + rv * APITCH + cv), r0, r1, r2, r3);
                bh[2*np][0]=r0; bh[2*np][1]=r1; bh[2*np+1][0]=r2; bh[2*np+1][1]=r3;
                ldsm4t(smem_u32(Vl + rv * APITCH + cv), r0, r1, r2, r3);
                bl[2*np][0]=r0; bl[2*np][1]=r1; bl[2*np+1][0]=r2; bl[2*np+1][1]=r3;
            }
            #pragma unroll
            for (int nt = 0; nt < 8; nt++) {
                mma_bf16(oacc[nt], ah, bh[nt]);
                mma_bf16(oacc[nt], ah, bl[nt]);
                mma_bf16(oacc[nt], al, bh[nt]);
            }
        }
        __syncthreads();   // (C) slot s fully consumed
        if (it + 2 < NIT) loadKV((it + 2) * AKT, s);
    }

    // normalize + write split output
    const int r0 = wid * 16 + (lane >> 2);
    const float inv0 = 1.0f / dsum[r0];
    const float inv1 = 1.0f / dsum[r0 + 8];
    #pragma unroll
    for (int nt = 0; nt < 8; nt++) {
        int c = nt * 8 + 2 * (lane & 3);
        size_t i0 = (size_t)(b * NN + n0 + r0) * DD + h * HD + c;
        size_t i1 = (size_t)(b * NN + n0 + r0 + 8) * DD + h * HD + c;
        __nv_bfloat16 hh, ll;
        split2(oacc[nt][0] * inv0, hh, ll); g_ao_hi[i0]     = hh; g_ao_lo[i0]     = ll;
        split2(oacc[nt][1] * inv0, hh, ll); g_ao_hi[i0 + 1] = hh; g_ao_lo[i0 + 1] = ll;
        split2(oacc[nt][2] * inv1, hh, ll); g_ao_hi[i1]     = hh; g_ao_lo[i1]     = ll;
        split2(oacc[nt][3] * inv1, hh, ll); g_ao_hi[i1 + 1] = hh; g_ao_lo[i1 + 1] = ll;
    }
}

// ---------------------------------------------------------------------------
__global__ void finalize_mean(float* out, int out_size)
{
    const int base = BB * NN * DD;
    for (int i = base + threadIdx.x; i < out_size; i += blockDim.x)
        out[i] = 1.0f / (float)KC;
}

// ---------------------------------------------------------------------------
extern "C" void kernel_launch(void* const* d_in, const int* in_sizes, int n_in,
                              void* d_out, int out_size)
{
    const float* x      = (const float*)d_in[0];
    const float* ctx    = (const float*)d_in[1];
    const float* q_w    = (const float*)d_in[2];
    const float* q_b    = (const float*)d_in[3];
    const float* kv_w   = (const float*)d_in[4];
    const float* kv_b   = (const float*)d_in[5];
    const float* proj_w = (const float*)d_in[6];
    const float* proj_b = (const float*)d_in[7];
    float* out = (float*)d_out;

    __nv_bfloat16 *xh,*xl,*qwh,*qwl,*kvwh,*kvwl,*pwh,*pwl,*cnh,*cnl,*qh,*ql,*kvh,*kvl,*aoh,*aol;
    cudaGetSymbolAddress((void**)&xh,  g_x_hi);  cudaGetSymbolAddress((void**)&xl,  g_x_lo);
    cudaGetSymbolAddress((void**)&qwh, g_qw_hi); cudaGetSymbolAddress((void**)&qwl, g_qw_lo);
    cudaGetSymbolAddress((void**)&kvwh,g_kvw_hi);cudaGetSymbolAddress((void**)&kvwl,g_kvw_lo);
    cudaGetSymbolAddress((void**)&pwh, g_pw_hi); cudaGetSymbolAddress((void**)&pwl, g_pw_lo);
    cudaGetSymbolAddress((void**)&cnh, g_cn_hi); cudaGetSymbolAddress((void**)&cnl, g_cn_lo);
    cudaGetSymbolAddress((void**)&qh,  g_q_hi);  cudaGetSymbolAddress((void**)&ql,  g_q_lo);
    cudaGetSymbolAddress((void**)&kvh, g_kv_hi); cudaGetSymbolAddress((void**)&kvl, g_kv_lo);
    cudaGetSymbolAddress((void**)&aoh, g_ao_hi); cudaGetSymbolAddress((void**)&aol, g_ao_lo);

    cudaFuncSetAttribute(mmgemm<true>,  cudaFuncAttributeMaxDynamicSharedMemorySize, GEMM_SMEM);
    cudaFuncSetAttribute(mmgemm<false>, cudaFuncAttributeMaxDynamicSharedMemorySize, GEMM_SMEM);
    cudaFuncSetAttribute(attn_mma,      cudaFuncAttributeMaxDynamicSharedMemorySize, ATTN_SMEM);

    split_kernel<<<(BB*NN*DD/4 + 255)/256, 256>>>(x, xh, xl, BB*NN*DD);
    split_kernel<<<(DD*DD/4 + 255)/256, 256>>>(q_w, qwh, qwl, DD*DD);
    split_kernel<<<(DD*2*DD/4 + 255)/256, 256>>>(kv_w, kvwh, kvwl, DD*2*DD);
    split_kernel<<<(DD*DD/4 + 255)/256, 256>>>(proj_w, pwh, pwl, DD*DD);

    rmsnorm_split<<<BB*KC, 256>>>(ctx);

    // q = (x @ q_w + q_b) * 0.125  -> split
    mmgemm<true><<<dim3(DD/GBN, BB*NN/GBM), 256, GEMM_SMEM>>>(
        xh, xl, qwh, qwl, q_b, 0.125f, nullptr, qh, ql, BB*NN, DD, DD);

    // kv = ctxn @ kv_w + kv_b  -> split
    mmgemm<true><<<dim3(2*DD/GBN, BB*KC/GBM), 256, GEMM_SMEM>>>(
        cnh, cnl, kvwh, kvwl, kv_b, 1.0f, nullptr, kvh, kvl, BB*KC, 2*DD, DD);

    // attention
    attn_mma<<<dim3(BB*HH, NN/ANT), 256, ATTN_SMEM>>>();

    // out = attn @ proj_w + proj_b (fp32)
    mmgemm<false><<<dim3(DD/GBN, BB*NN/GBM), 256, GEMM_SMEM>>>(
        aoh, aol, pwh, pwl, proj_b, 1.0f, out, nullptr, nullptr, BB*NN, DD, DD);

    if (out_size > BB * NN * DD)
        finalize_mean<<<1, 32>>>(out, out_size);
}

// round 6
// speedup vs baseline: 1.1135x; 1.1135x over previous
#include <cuda_runtime.h>
#include <cuda_bf16.h>
#include <cstdint>

#define BB 4
#define NN 2048
#define KC 2048
#define DD 1024
#define HH 16
#define HD 64
#define RMS_EPS 1e-6f

// ---------------------------------------------------------------------------
// Scratch (bf16 hi/lo split arrays)
// ---------------------------------------------------------------------------
__device__ __nv_bfloat16 g_x_hi[BB*NN*DD],   g_x_lo[BB*NN*DD];
__device__ __nv_bfloat16 g_qw_hi[DD*DD],     g_qw_lo[DD*DD];
__device__ __nv_bfloat16 g_kvw_hi[DD*2*DD],  g_kvw_lo[DD*2*DD];
__device__ __nv_bfloat16 g_pw_hi[DD*DD],     g_pw_lo[DD*DD];
__device__ __nv_bfloat16 g_cn_hi[BB*KC*DD],  g_cn_lo[BB*KC*DD];
__device__ __nv_bfloat16 g_q_hi[BB*NN*DD],   g_q_lo[BB*NN*DD];      // pre-scaled 0.125
__device__ __nv_bfloat16 g_kv_hi[BB*KC*2*DD],g_kv_lo[BB*KC*2*DD];
__device__ __nv_bfloat16 g_ao_hi[BB*NN*DD],  g_ao_lo[BB*NN*DD];

// ---------------------------------------------------------------------------
// PTX helpers
// ---------------------------------------------------------------------------
__device__ __forceinline__ uint32_t smem_u32(const void* p) {
    return (uint32_t)__cvta_generic_to_shared(p);
}
__device__ __forceinline__ void ldsm4(uint32_t a, uint32_t& r0, uint32_t& r1,
                                      uint32_t& r2, uint32_t& r3) {
    asm volatile("ldmatrix.sync.aligned.m8n8.x4.shared.b16 {%0,%1,%2,%3}, [%4];"
                 : "=r"(r0), "=r"(r1), "=r"(r2), "=r"(r3) : "r"(a));
}
__device__ __forceinline__ void ldsm4t(uint32_t a, uint32_t& r0, uint32_t& r1,
                                       uint32_t& r2, uint32_t& r3) {
    asm volatile("ldmatrix.sync.aligned.m8n8.x4.trans.shared.b16 {%0,%1,%2,%3}, [%4];"
                 : "=r"(r0), "=r"(r1), "=r"(r2), "=r"(r3) : "r"(a));
}
__device__ __forceinline__ void mma_bf16(float* c, const uint32_t* a, const uint32_t* b) {
    asm volatile(
        "mma.sync.aligned.m16n8k16.row.col.f32.bf16.bf16.f32 "
        "{%0,%1,%2,%3},{%4,%5,%6,%7},{%8,%9},{%0,%1,%2,%3};\n"
        : "+f"(c[0]), "+f"(c[1]), "+f"(c[2]), "+f"(c[3])
        : "r"(a[0]), "r"(a[1]), "r"(a[2]), "r"(a[3]), "r"(b[0]), "r"(b[1]));
}
__device__ __forceinline__ void cpa16(void* dst, const void* src) {
    uint32_t d = smem_u32(dst);
    asm volatile("cp.async.cg.shared.global [%0], [%1], 16;\n" :: "r"(d), "l"(src));
}
__device__ __forceinline__ void split2(float v, __nv_bfloat16& h, __nv_bfloat16& l) {
    h = __float2bfloat16(v);
    l = __float2bfloat16(v - __bfloat162float(h));
}
__device__ __forceinline__ uint32_t packbf(float x, float y) {
    __nv_bfloat162 t = __floats2bfloat162_rn(x, y);   // .x = x in low half
    return *reinterpret_cast<uint32_t*>(&t);
}

// ---------------------------------------------------------------------------
// fp32 -> bf16 hi/lo split
// ---------------------------------------------------------------------------
__global__ __launch_bounds__(256) void split_kernel(const float* __restrict__ src,
                                                    __nv_bfloat16* __restrict__ hi,
                                                    __nv_bfloat16* __restrict__ lo, int n)
{
    int i = (blockIdx.x * 256 + threadIdx.x) * 4;
    if (i >= n) return;
    float4 v = *reinterpret_cast<const float4*>(src + i);
    __nv_bfloat16 h0,l0,h1,l1,h2,l2,h3,l3;
    split2(v.x,h0,l0); split2(v.y,h1,l1); split2(v.z,h2,l2); split2(v.w,h3,l3);
    hi[i]=h0; hi[i+1]=h1; hi[i+2]=h2; hi[i+3]=h3;
    lo[i]=l0; lo[i+1]=l1; lo[i+2]=l2; lo[i+3]=l3;
}

// ---------------------------------------------------------------------------
// RMSNorm -> bf16 hi/lo
// ---------------------------------------------------------------------------
__global__ __launch_bounds__(256) void rmsnorm_split(const float* __restrict__ ctx)
{
    const int row = blockIdx.x;
    float4 v = reinterpret_cast<const float4*>(ctx + (size_t)row * DD)[threadIdx.x];
    float s = v.x*v.x + v.y*v.y + v.z*v.z + v.w*v.w;
    #pragma unroll
    for (int o = 16; o > 0; o >>= 1) s += __shfl_xor_sync(0xffffffffu, s, o);
    __shared__ float ws[8];
    if ((threadIdx.x & 31) == 0) ws[threadIdx.x >> 5] = s;
    __syncthreads();
    float tot = 0.f;
    #pragma unroll
    for (int i = 0; i < 8; i++) tot += ws[i];
    const float r = rsqrtf(tot * (1.0f / (float)DD) + RMS_EPS);
    const size_t base = (size_t)row * DD + threadIdx.x * 4;
    __nv_bfloat16 h, l;
    split2(v.x*r,h,l); g_cn_hi[base+0]=h; g_cn_lo[base+0]=l;
    split2(v.y*r,h,l); g_cn_hi[base+1]=h; g_cn_lo[base+1]=l;
    split2(v.z*r,h,l); g_cn_hi[base+2]=h; g_cn_lo[base+2]=l;
    split2(v.w*r,h,l); g_cn_hi[base+3]=h; g_cn_lo[base+3]=l;
}

// ---------------------------------------------------------------------------
// Split-bf16 GEMM (validated R3): C = (Ahi+Alo)@(Whi+Wlo) + bias
// tile 128x128x32, 256 threads, double-buffered cp.async.
// ---------------------------------------------------------------------------
#define GBM 128
#define GBN 128
#define GBK 32
#define APAD 40
#define WPAD 136
#define A_EL (GBM*APAD)
#define W_EL (GBK*WPAD)
#define STG_EL (2*A_EL + 2*W_EL)
#define GEMM_SMEM (2*STG_EL*2)

template<bool SPLIT>
__global__ __launch_bounds__(256, 1) void mmgemm(
    const __nv_bfloat16* __restrict__ Ahi, const __nv_bfloat16* __restrict__ Alo,
    const __nv_bfloat16* __restrict__ Whi, const __nv_bfloat16* __restrict__ Wlo,
    const float* __restrict__ bias, float scale,
    float* __restrict__ Cf, __nv_bfloat16* __restrict__ Chi, __nv_bfloat16* __restrict__ Clo,
    int M, int N, int K)
{
    extern __shared__ __nv_bfloat16 sm[];
    const int tid = threadIdx.x;
    const int wid = tid >> 5, lane = tid & 31;
    const int rowBase = blockIdx.y * GBM;
    const int colBase = blockIdx.x * GBN;
    const int wm = wid & 3;
    const int wn = wid >> 2;

    auto loadStage = [&](int kc, int s) {
        const int k0 = kc * GBK;
        __nv_bfloat16* Ah = sm + s * STG_EL;
        __nv_bfloat16* Al = Ah + A_EL;
        __nv_bfloat16* Wh = Al + A_EL;
        __nv_bfloat16* Wl = Wh + W_EL;
        #pragma unroll
        for (int i = 0; i < 2; i++) {
            int t = tid + i * 256;
            int r = t >> 2, ch = t & 3;
            size_t ga = (size_t)(rowBase + r) * K + k0 + ch * 8;
            cpa16(Ah + r * APAD + ch * 8, Ahi + ga);
            cpa16(Al + r * APAD + ch * 8, Alo + ga);
            int rw = t >> 4, cw = t & 15;
            size_t gw = (size_t)(k0 + rw) * N + colBase + cw * 8;
            cpa16(Wh + rw * WPAD + cw * 8, Whi + gw);
            cpa16(Wl + rw * WPAD + cw * 8, Wlo + gw);
        }
        asm volatile("cp.async.commit_group;\n");
    };

    float acc[2][8][4];
    #pragma unroll
    for (int mt = 0; mt < 2; mt++)
        #pragma unroll
        for (int nt = 0; nt < 8; nt++)
            #pragma unroll
            for (int e = 0; e < 4; e++) acc[mt][nt][e] = 0.f;

    const int NK = K / GBK;
    loadStage(0, 0);
    for (int kc = 0; kc < NK; kc++) {
        if (kc + 1 < NK) {
            loadStage(kc + 1, (kc + 1) & 1);
            asm volatile("cp.async.wait_group 1;\n");
        } else {
            asm volatile("cp.async.wait_group 0;\n");
        }
        __syncthreads();

        __nv_bfloat16* Ah = sm + (kc & 1) * STG_EL;
        __nv_bfloat16* Al = Ah + A_EL;
        __nv_bfloat16* Wh = Al + A_EL;
        __nv_bfloat16* Wl = Wh + W_EL;

        #pragma unroll
        for (int k16 = 0; k16 < 2; k16++) {
            const int kk = k16 * 16;
            uint32_t ah[2][4], al[2][4];
            #pragma unroll
            for (int mt = 0; mt < 2; mt++) {
                int r = wm * 32 + mt * 16 + (lane & 7) + ((lane >> 3) & 1) * 8;
                int c = kk + (lane >> 4) * 8;
                ldsm4(smem_u32(Ah + r * APAD + c), ah[mt][0], ah[mt][1], ah[mt][2], ah[mt][3]);
                ldsm4(smem_u32(Al + r * APAD + c), al[mt][0], al[mt][1], al[mt][2], al[mt][3]);
            }
            uint32_t bh[8][2], bl[8][2];
            #pragma unroll
            for (int np = 0; np < 4; np++) {
                int r = kk + (lane & 7) + ((lane >> 3) & 1) * 8;
                int c = wn * 64 + np * 16 + (lane >> 4) * 8;
                uint32_t r0, r1, r2, r3;
                ldsm4t(smem_u32(Wh + r * WPAD + c), r0, r1, r2, r3);
                bh[2*np][0]=r0; bh[2*np][1]=r1; bh[2*np+1][0]=r2; bh[2*np+1][1]=r3;
                ldsm4t(smem_u32(Wl + r * WPAD + c), r0, r1, r2, r3);
                bl[2*np][0]=r0; bl[2*np][1]=r1; bl[2*np+1][0]=r2; bl[2*np+1][1]=r3;
            }
            #pragma unroll
            for (int mt = 0; mt < 2; mt++)
                #pragma unroll
                for (int nt = 0; nt < 8; nt++) {
                    mma_bf16(acc[mt][nt], ah[mt], bh[nt]);
                    mma_bf16(acc[mt][nt], ah[mt], bl[nt]);
                    mma_bf16(acc[mt][nt], al[mt], bh[nt]);
                }
        }
        __syncthreads();
    }

    #pragma unroll
    for (int mt = 0; mt < 2; mt++)
        #pragma unroll
        for (int nt = 0; nt < 8; nt++) {
            int row = rowBase + wm * 32 + mt * 16 + (lane >> 2);
            int col = colBase + wn * 64 + nt * 8 + 2 * (lane & 3);
            float b0 = bias[col], b1 = bias[col + 1];
            float v00 = (acc[mt][nt][0] + b0) * scale;
            float v01 = (acc[mt][nt][1] + b1) * scale;
            float v10 = (acc[mt][nt][2] + b0) * scale;
            float v11 = (acc[mt][nt][3] + b1) * scale;
            size_t i0 = (size_t)row * N + col;
            size_t i1 = (size_t)(row + 8) * N + col;
            if (SPLIT) {
                __nv_bfloat16 h, l;
                split2(v00, h, l); Chi[i0]     = h; Clo[i0]     = l;
                split2(v01, h, l); Chi[i0 + 1] = h; Clo[i0 + 1] = l;
                split2(v10, h, l); Chi[i1]     = h; Clo[i1]     = l;
                split2(v11, h, l); Chi[i1 + 1] = h; Clo[i1 + 1] = l;
            } else {
                Cf[i0] = v00; Cf[i0 + 1] = v01;
                Cf[i1] = v10; Cf[i1 + 1] = v11;
            }
        }
}

// ---------------------------------------------------------------------------
// Attention v2: register-direct P (no P smem round-trip, no smem dsum),
// 2 syncs/iter, 2 CTAs/SM. Block = (b,h, 128 q-rows); 8 warps; kc tiles of 64.
// smem: Qh/Ql 128x72 + 2 stages of (Kh,Kl,Vh,Vl) 64x72  = 110592 B
// ---------------------------------------------------------------------------
#define ANT 128
#define AKT 64
#define APITCH 72
#define Q_EL (ANT*APITCH)            // 9216
#define KV_ARR (AKT*APITCH)          // 4608
#define KV_STAGE (4*KV_ARR)          // 18432
#define ATTN_SMEM ((2*Q_EL + 2*KV_STAGE) * 2)

__global__ __launch_bounds__(256, 2) void attn_mma()
{
    extern __shared__ __nv_bfloat16 smb[];
    __nv_bfloat16* Qh = smb;
    __nv_bfloat16* Ql = Qh + Q_EL;
    __nv_bfloat16* KV = Ql + Q_EL;          // stage s at KV + s*KV_STAGE

    const int tid = threadIdx.x, wid = tid >> 5, lane = tid & 31;
    const int b = blockIdx.x >> 4, h = blockIdx.x & 15;
    const int n0 = blockIdx.y * ANT;

    auto loadKV = [&](int kc0, int s) {
        __nv_bfloat16* base = KV + s * KV_STAGE;
        #pragma unroll
        for (int i = 0; i < 2; i++) {
            int t = tid + i * 256;
            int r = t >> 3, ch = t & 7;
            size_t gk = (size_t)(b * KC + kc0 + r) * (2 * DD) + h * HD + ch * 8;
            cpa16(base +            r * APITCH + ch * 8, g_kv_hi + gk);
            cpa16(base + KV_ARR   + r * APITCH + ch * 8, g_kv_lo + gk);
            cpa16(base + 2*KV_ARR + r * APITCH + ch * 8, g_kv_hi + gk + DD);
            cpa16(base + 3*KV_ARR + r * APITCH + ch * 8, g_kv_lo + gk + DD);
        }
        asm volatile("cp.async.commit_group;\n");
    };

    // Q via cp.async (folded into group 0 with first KV tile)
    #pragma unroll
    for (int i = 0; i < 4; i++) {
        int t = tid + i * 256;
        int r = t >> 3, ch = t & 7;
        size_t g = (size_t)(b * NN + n0 + r) * DD + h * HD + ch * 8;
        cpa16(Qh + r * APITCH + ch * 8, g_q_hi + g);
        cpa16(Ql + r * APITCH + ch * 8, g_q_lo + g);
    }
    loadKV(0, 0);        // group 0 (Q + KV tile 0)
    loadKV(AKT, 1);      // group 1

    float oacc[8][4];
    #pragma unroll
    for (int nt = 0; nt < 8; nt++)
        #pragma unroll
        for (int e = 0; e < 4; e++) oacc[nt][e] = 0.f;
    float d0 = 0.f, d1 = 0.f;   // per-thread partial row sums (rows r, r+8)

    const int NIT = KC / AKT;   // 32
    for (int it = 0; it < NIT; it++) {
        const int s = it & 1;
        __nv_bfloat16* Kh = KV + s * KV_STAGE;
        __nv_bfloat16* Kl = Kh + KV_ARR;
        __nv_bfloat16* Vh = Kh + 2*KV_ARR;
        __nv_bfloat16* Vl = Kh + 3*KV_ARR;

        if (it + 1 < NIT) asm volatile("cp.async.wait_group 1;\n");
        else              asm volatile("cp.async.wait_group 0;\n");
        __syncthreads();   // (A) stage s data visible

        // ---- S = Q @ K^T ----
        float sacc[8][4];
        #pragma unroll
        for (int nt = 0; nt < 8; nt++)
            #pragma unroll
            for (int e = 0; e < 4; e++) sacc[nt][e] = 0.f;

        #pragma unroll
        for (int d16 = 0; d16 < 4; d16++) {
            const int dd0 = d16 * 16;
            uint32_t ah[4], al[4];
            {
                int r = wid * 16 + (lane & 7) + ((lane >> 3) & 1) * 8;
                int c = dd0 + (lane >> 4) * 8;
                ldsm4(smem_u32(Qh + r * APITCH + c), ah[0], ah[1], ah[2], ah[3]);
                ldsm4(smem_u32(Ql + r * APITCH + c), al[0], al[1], al[2], al[3]);
            }
            uint32_t bh[8][2], bl[8][2];
            #pragma unroll
            for (int np = 0; np < 4; np++) {
                int r = np * 16 + (lane & 7) + ((lane >> 4)) * 8;
                int c = dd0 + ((lane >> 3) & 1) * 8;
                uint32_t r0, r1, r2, r3;
                ldsm4(smem_u32(Kh + r * APITCH + c), r0, r1, r2, r3);
                bh[2*np][0]=r0; bh[2*np][1]=r1; bh[2*np+1][0]=r2; bh[2*np+1][1]=r3;
                ldsm4(smem_u32(Kl + r * APITCH + c), r0, r1, r2, r3);
                bl[2*np][0]=r0; bl[2*np][1]=r1; bl[2*np+1][0]=r2; bl[2*np+1][1]=r3;
            }
            #pragma unroll
            for (int nt = 0; nt < 8; nt++) {
                mma_bf16(sacc[nt], ah, bh[nt]);
                mma_bf16(sacc[nt], ah, bl[nt]);
                mma_bf16(sacc[nt], al, bh[nt]);
            }
        }

        // ---- P = exp(clip(S)) in registers + partial row sums ----
        #pragma unroll
        for (int nt = 0; nt < 8; nt++) {
            #pragma unroll
            for (int e = 0; e < 4; e++)
                sacc[nt][e] = __expf(fminf(fmaxf(sacc[nt][e], -10.f), 10.f));
            d0 += sacc[nt][0] + sacc[nt][1];
            d1 += sacc[nt][2] + sacc[nt][3];
        }

        // ---- O += P @ V : accumulator fragments ARE the PV A-fragments ----
        #pragma unroll
        for (int c16 = 0; c16 < 4; c16++) {
            const int kk = c16 * 16;
            // pack P hi/lo fragments from the two S-tiles covering kc [kk, kk+16)
            uint32_t ah[4], al[4];
            {
                const float* t0 = sacc[2*c16];
                const float* t1 = sacc[2*c16 + 1];
                __nv_bfloat162 h;
                h = __floats2bfloat162_rn(t0[0], t0[1]);
                ah[0] = *reinterpret_cast<uint32_t*>(&h);
                al[0] = packbf(t0[0] - __bfloat162float(h.x), t0[1] - __bfloat162float(h.y));
                h = __floats2bfloat162_rn(t0[2], t0[3]);
                ah[1] = *reinterpret_cast<uint32_t*>(&h);
                al[1] = packbf(t0[2] - __bfloat162float(h.x), t0[3] - __bfloat162float(h.y));
                h = __floats2bfloat162_rn(t1[0], t1[1]);
                ah[2] = *reinterpret_cast<uint32_t*>(&h);
                al[2] = packbf(t1[0] - __bfloat162float(h.x), t1[1] - __bfloat162float(h.y));
                h = __floats2bfloat162_rn(t1[2], t1[3]);
                ah[3] = *reinterpret_cast<uint32_t*>(&h);
                al[3] = packbf(t1[2] - __bfloat162float(h.x), t1[3] - __bfloat162float(h.y));
            }
            uint32_t bh[8][2], bl[8][2];
            #pragma unroll
            for (int np = 0; np < 4; np++) {
                int rv = kk + (lane & 7) + ((lane >> 3) & 1) * 8;
                int cv = np * 16 + (lane >> 4) * 8;
                uint32_t r0, r1, r2, r3;
                ldsm4t(smem_u32(Vh + rv * APITCH + cv), r0, r1, r2, r3);
                bh[2*np][0]=r0; bh[2*np][1]=r1; bh[2*np+1][0]=r2; bh[2*np+1][1]=r3;
                ldsm4t(smem_u32(Vl + rv * APITCH + cv), r0, r1, r2, r3);
                bl[2*np][0]=r0; bl[2*np][1]=r1; bl[2*np+1][0]=r2; bl[2*np+1][1]=r3;
            }
            #pragma unroll
            for (int nt = 0; nt < 8; nt++) {
                mma_bf16(oacc[nt], ah, bh[nt]);
                mma_bf16(oacc[nt], ah, bl[nt]);
                mma_bf16(oacc[nt], al, bh[nt]);
            }
        }
        __syncthreads();   // (B) stage s fully consumed
        if (it + 2 < NIT) loadKV((it + 2) * AKT, s);
    }

    // reduce row sums across the quad (lanes differing in bits 0,1 share a row)
    d0 += __shfl_xor_sync(0xffffffffu, d0, 1);
    d0 += __shfl_xor_sync(0xffffffffu, d0, 2);
    d1 += __shfl_xor_sync(0xffffffffu, d1, 1);
    d1 += __shfl_xor_sync(0xffffffffu, d1, 2);
    const float inv0 = 1.0f / d0;
    const float inv1 = 1.0f / d1;

    // normalize + write split output
    const int r0 = wid * 16 + (lane >> 2);
    #pragma unroll
    for (int nt = 0; nt < 8; nt++) {
        int c = nt * 8 + 2 * (lane & 3);
        size_t i0 = (size_t)(b * NN + n0 + r0) * DD + h * HD + c;
        size_t i1 = (size_t)(b * NN + n0 + r0 + 8) * DD + h * HD + c;
        __nv_bfloat16 hh, ll;
        split2(oacc[nt][0] * inv0, hh, ll); g_ao_hi[i0]     = hh; g_ao_lo[i0]     = ll;
        split2(oacc[nt][1] * inv0, hh, ll); g_ao_hi[i0 + 1] = hh; g_ao_lo[i0 + 1] = ll;
        split2(oacc[nt][2] * inv1, hh, ll); g_ao_hi[i1]     = hh; g_ao_lo[i1]     = ll;
        split2(oacc[nt][3] * inv1, hh, ll); g_ao_hi[i1 + 1] = hh; g_ao_lo[i1 + 1] = ll;
    }
}

// ---------------------------------------------------------------------------
__global__ void finalize_mean(float* out, int out_size)
{
    const int base = BB * NN * DD;
    for (int i = base + threadIdx.x; i < out_size; i += blockDim.x)
        out[i] = 1.0f / (float)KC;
}

// ---------------------------------------------------------------------------
extern "C" void kernel_launch(void* const* d_in, const int* in_sizes, int n_in,
                              void* d_out, int out_size)
{
    const float* x      = (const float*)d_in[0];
    const float* ctx    = (const float*)d_in[1];
    const float* q_w    = (const float*)d_in[2];
    const float* q_b    = (const float*)d_in[3];
    const float* kv_w   = (const float*)d_in[4];
    const float* kv_b   = (const float*)d_in[5];
    const float* proj_w = (const float*)d_in[6];
    const float* proj_b = (const float*)d_in[7];
    float* out = (float*)d_out;

    __nv_bfloat16 *xh,*xl,*qwh,*qwl,*kvwh,*kvwl,*pwh,*pwl,*cnh,*cnl,*qh,*ql,*kvh,*kvl,*aoh,*aol;
    cudaGetSymbolAddress((void**)&xh,  g_x_hi);  cudaGetSymbolAddress((void**)&xl,  g_x_lo);
    cudaGetSymbolAddress((void**)&qwh, g_qw_hi); cudaGetSymbolAddress((void**)&qwl, g_qw_lo);
    cudaGetSymbolAddress((void**)&kvwh,g_kvw_hi);cudaGetSymbolAddress((void**)&kvwl,g_kvw_lo);
    cudaGetSymbolAddress((void**)&pwh, g_pw_hi); cudaGetSymbolAddress((void**)&pwl, g_pw_lo);
    cudaGetSymbolAddress((void**)&cnh, g_cn_hi); cudaGetSymbolAddress((void**)&cnl, g_cn_lo);
    cudaGetSymbolAddress((void**)&qh,  g_q_hi);  cudaGetSymbolAddress((void**)&ql,  g_q_lo);
    cudaGetSymbolAddress((void**)&kvh, g_kv_hi); cudaGetSymbolAddress((void**)&kvl, g_kv_lo);
    cudaGetSymbolAddress((void**)&aoh, g_ao_hi); cudaGetSymbolAddress((void**)&aol, g_ao_lo);

    cudaFuncSetAttribute(mmgemm<true>,  cudaFuncAttributeMaxDynamicSharedMemorySize, GEMM_SMEM);
    cudaFuncSetAttribute(mmgemm<false>, cudaFuncAttributeMaxDynamicSharedMemorySize, GEMM_SMEM);
    cudaFuncSetAttribute(attn_mma,      cudaFuncAttributeMaxDynamicSharedMemorySize, ATTN_SMEM);

    split_kernel<<<(BB*NN*DD/4 + 255)/256, 256>>>(x, xh, xl, BB*NN*DD);
    split_kernel<<<(DD*DD/4 + 255)/256, 256>>>(q_w, qwh, qwl, DD*DD);
    split_kernel<<<(DD*2*DD/4 + 255)/256, 256>>>(kv_w, kvwh, kvwl, DD*2*DD);
    split_kernel<<<(DD*DD/4 + 255)/256, 256>>>(proj_w, pwh, pwl, DD*DD);

    rmsnorm_split<<<BB*KC, 256>>>(ctx);

    // q = (x @ q_w + q_b) * 0.125  -> split
    mmgemm<true><<<dim3(DD/GBN, BB*NN/GBM), 256, GEMM_SMEM>>>(
        xh, xl, qwh, qwl, q_b, 0.125f, nullptr, qh, ql, BB*NN, DD, DD);

    // kv = ctxn @ kv_w + kv_b  -> split
    mmgemm<true><<<dim3(2*DD/GBN, BB*KC/GBM), 256, GEMM_SMEM>>>(
        cnh, cnl, kvwh, kvwl, kv_b, 1.0f, nullptr, kvh, kvl, BB*KC, 2*DD, DD);

    // attention
    attn_mma<<<dim3(BB*HH, NN/ANT), 256, ATTN_SMEM>>>();

    // out = attn @ proj_w + proj_b (fp32)
    mmgemm<false><<<dim3(DD/GBN, BB*NN/GBM), 256, GEMM_SMEM>>>(
        aoh, aol, pwh, pwl, proj_b, 1.0f, out, nullptr, nullptr, BB*NN, DD, DD);

    if (out_size > BB * NN * DD)
        finalize_mean<<<1, 32>>>(out, out_size);
}

// round 7
// speedup vs baseline: 1.2163x; 1.0923x over previous
#include <cuda_runtime.h>
#include <cuda_bf16.h>
#include <cstdint>

#define BB 4
#define NN 2048
#define KC 2048
#define DD 1024
#define HH 16
#define HD 64
#define RMS_EPS 1e-6f

// ---------------------------------------------------------------------------
// Scratch (bf16 hi/lo split arrays)
// ---------------------------------------------------------------------------
__device__ __nv_bfloat16 g_x_hi[BB*NN*DD],   g_x_lo[BB*NN*DD];
__device__ __nv_bfloat16 g_qw_hi[DD*DD],     g_qw_lo[DD*DD];
__device__ __nv_bfloat16 g_kvw_hi[DD*2*DD],  g_kvw_lo[DD*2*DD];
__device__ __nv_bfloat16 g_pw_hi[DD*DD],     g_pw_lo[DD*DD];
__device__ __nv_bfloat16 g_cn_hi[BB*KC*DD],  g_cn_lo[BB*KC*DD];
__device__ __nv_bfloat16 g_q_hi[BB*NN*DD],   g_q_lo[BB*NN*DD];      // pre-scaled 0.125
__device__ __nv_bfloat16 g_kv_hi[BB*KC*2*DD],g_kv_lo[BB*KC*2*DD];
__device__ __nv_bfloat16 g_ao_hi[BB*NN*DD],  g_ao_lo[BB*NN*DD];

// ---------------------------------------------------------------------------
// PTX helpers
// ---------------------------------------------------------------------------
__device__ __forceinline__ uint32_t smem_u32(const void* p) {
    return (uint32_t)__cvta_generic_to_shared(p);
}
__device__ __forceinline__ void ldsm4(uint32_t a, uint32_t& r0, uint32_t& r1,
                                      uint32_t& r2, uint32_t& r3) {
    asm volatile("ldmatrix.sync.aligned.m8n8.x4.shared.b16 {%0,%1,%2,%3}, [%4];"
                 : "=r"(r0), "=r"(r1), "=r"(r2), "=r"(r3) : "r"(a));
}
__device__ __forceinline__ void ldsm4t(uint32_t a, uint32_t& r0, uint32_t& r1,
                                       uint32_t& r2, uint32_t& r3) {
    asm volatile("ldmatrix.sync.aligned.m8n8.x4.trans.shared.b16 {%0,%1,%2,%3}, [%4];"
                 : "=r"(r0), "=r"(r1), "=r"(r2), "=r"(r3) : "r"(a));
}
__device__ __forceinline__ void mma_bf16(float* c, const uint32_t* a, const uint32_t* b) {
    asm volatile(
        "mma.sync.aligned.m16n8k16.row.col.f32.bf16.bf16.f32 "
        "{%0,%1,%2,%3},{%4,%5,%6,%7},{%8,%9},{%0,%1,%2,%3};\n"
        : "+f"(c[0]), "+f"(c[1]), "+f"(c[2]), "+f"(c[3])
        : "r"(a[0]), "r"(a[1]), "r"(a[2]), "r"(a[3]), "r"(b[0]), "r"(b[1]));
}
__device__ __forceinline__ void cpa16(void* dst, const void* src) {
    uint32_t d = smem_u32(dst);
    asm volatile("cp.async.cg.shared.global [%0], [%1], 16;\n" :: "r"(d), "l"(src));
}
__device__ __forceinline__ void split2(float v, __nv_bfloat16& h, __nv_bfloat16& l) {
    h = __float2bfloat16(v);
    l = __float2bfloat16(v - __bfloat162float(h));
}
__device__ __forceinline__ uint32_t packbf(float x, float y) {
    __nv_bfloat162 t = __floats2bfloat162_rn(x, y);   // .x = x in low half
    return *reinterpret_cast<uint32_t*>(&t);
}

// ---------------------------------------------------------------------------
// fp32 -> bf16 hi/lo split
// ---------------------------------------------------------------------------
__global__ __launch_bounds__(256) void split_kernel(const float* __restrict__ src,
                                                    __nv_bfloat16* __restrict__ hi,
                                                    __nv_bfloat16* __restrict__ lo, int n)
{
    int i = (blockIdx.x * 256 + threadIdx.x) * 4;
    if (i >= n) return;
    float4 v = *reinterpret_cast<const float4*>(src + i);
    __nv_bfloat16 h0,l0,h1,l1,h2,l2,h3,l3;
    split2(v.x,h0,l0); split2(v.y,h1,l1); split2(v.z,h2,l2); split2(v.w,h3,l3);
    hi[i]=h0; hi[i+1]=h1; hi[i+2]=h2; hi[i+3]=h3;
    lo[i]=l0; lo[i+1]=l1; lo[i+2]=l2; lo[i+3]=l3;
}

// ---------------------------------------------------------------------------
// RMSNorm -> bf16 hi/lo
// ---------------------------------------------------------------------------
__global__ __launch_bounds__(256) void rmsnorm_split(const float* __restrict__ ctx)
{
    const int row = blockIdx.x;
    float4 v = reinterpret_cast<const float4*>(ctx + (size_t)row * DD)[threadIdx.x];
    float s = v.x*v.x + v.y*v.y + v.z*v.z + v.w*v.w;
    #pragma unroll
    for (int o = 16; o > 0; o >>= 1) s += __shfl_xor_sync(0xffffffffu, s, o);
    __shared__ float ws[8];
    if ((threadIdx.x & 31) == 0) ws[threadIdx.x >> 5] = s;
    __syncthreads();
    float tot = 0.f;
    #pragma unroll
    for (int i = 0; i < 8; i++) tot += ws[i];
    const float r = rsqrtf(tot * (1.0f / (float)DD) + RMS_EPS);
    const size_t base = (size_t)row * DD + threadIdx.x * 4;
    __nv_bfloat16 h, l;
    split2(v.x*r,h,l); g_cn_hi[base+0]=h; g_cn_lo[base+0]=l;
    split2(v.y*r,h,l); g_cn_hi[base+1]=h; g_cn_lo[base+1]=l;
    split2(v.z*r,h,l); g_cn_hi[base+2]=h; g_cn_lo[base+2]=l;
    split2(v.w*r,h,l); g_cn_hi[base+3]=h; g_cn_lo[base+3]=l;
}

// ---------------------------------------------------------------------------
// Split-bf16 GEMM: C = (Ahi+Alo)@(Whi+Wlo) + bias
// tile 128x128x32, 256 threads, double-buffered cp.async, 2 CTAs/SM.
// ---------------------------------------------------------------------------
#define GBM 128
#define GBN 128
#define GBK 32
#define APAD 40
#define WPAD 136
#define A_EL (GBM*APAD)
#define W_EL (GBK*WPAD)
#define STG_EL (2*A_EL + 2*W_EL)
#define GEMM_SMEM (2*STG_EL*2)

template<bool SPLIT>
__global__ __launch_bounds__(256, 2) void mmgemm(
    const __nv_bfloat16* __restrict__ Ahi, const __nv_bfloat16* __restrict__ Alo,
    const __nv_bfloat16* __restrict__ Whi, const __nv_bfloat16* __restrict__ Wlo,
    const float* __restrict__ bias, float scale,
    float* __restrict__ Cf, __nv_bfloat16* __restrict__ Chi, __nv_bfloat16* __restrict__ Clo,
    int M, int N, int K)
{
    extern __shared__ __nv_bfloat16 sm[];
    const int tid = threadIdx.x;
    const int wid = tid >> 5, lane = tid & 31;
    const int rowBase = blockIdx.y * GBM;
    const int colBase = blockIdx.x * GBN;
    const int wm = wid & 3;
    const int wn = wid >> 2;

    auto loadStage = [&](int kc, int s) {
        const int k0 = kc * GBK;
        __nv_bfloat16* Ah = sm + s * STG_EL;
        __nv_bfloat16* Al = Ah + A_EL;
        __nv_bfloat16* Wh = Al + A_EL;
        __nv_bfloat16* Wl = Wh + W_EL;
        #pragma unroll
        for (int i = 0; i < 2; i++) {
            int t = tid + i * 256;
            int r = t >> 2, ch = t & 3;
            size_t ga = (size_t)(rowBase + r) * K + k0 + ch * 8;
            cpa16(Ah + r * APAD + ch * 8, Ahi + ga);
            cpa16(Al + r * APAD + ch * 8, Alo + ga);
            int rw = t >> 4, cw = t & 15;
            size_t gw = (size_t)(k0 + rw) * N + colBase + cw * 8;
            cpa16(Wh + rw * WPAD + cw * 8, Whi + gw);
            cpa16(Wl + rw * WPAD + cw * 8, Wlo + gw);
        }
        asm volatile("cp.async.commit_group;\n");
    };

    float acc[2][8][4];
    #pragma unroll
    for (int mt = 0; mt < 2; mt++)
        #pragma unroll
        for (int nt = 0; nt < 8; nt++)
            #pragma unroll
            for (int e = 0; e < 4; e++) acc[mt][nt][e] = 0.f;

    const int NK = K / GBK;
    loadStage(0, 0);
    for (int kc = 0; kc < NK; kc++) {
        if (kc + 1 < NK) {
            loadStage(kc + 1, (kc + 1) & 1);
            asm volatile("cp.async.wait_group 1;\n");
        } else {
            asm volatile("cp.async.wait_group 0;\n");
        }
        __syncthreads();

        __nv_bfloat16* Ah = sm + (kc & 1) * STG_EL;
        __nv_bfloat16* Al = Ah + A_EL;
        __nv_bfloat16* Wh = Al + A_EL;
        __nv_bfloat16* Wl = Wh + W_EL;

        #pragma unroll
        for (int k16 = 0; k16 < 2; k16++) {
            const int kk = k16 * 16;
            uint32_t ah[2][4], al[2][4];
            #pragma unroll
            for (int mt = 0; mt < 2; mt++) {
                int r = wm * 32 + mt * 16 + (lane & 7) + ((lane >> 3) & 1) * 8;
                int c = kk + (lane >> 4) * 8;
                ldsm4(smem_u32(Ah + r * APAD + c), ah[mt][0], ah[mt][1], ah[mt][2], ah[mt][3]);
                ldsm4(smem_u32(Al + r * APAD + c), al[mt][0], al[mt][1], al[mt][2], al[mt][3]);
            }
            uint32_t bh[8][2], bl[8][2];
            #pragma unroll
            for (int np = 0; np < 4; np++) {
                int r = kk + (lane & 7) + ((lane >> 3) & 1) * 8;
                int c = wn * 64 + np * 16 + (lane >> 4) * 8;
                uint32_t r0, r1, r2, r3;
                ldsm4t(smem_u32(Wh + r * WPAD + c), r0, r1, r2, r3);
                bh[2*np][0]=r0; bh[2*np][1]=r1; bh[2*np+1][0]=r2; bh[2*np+1][1]=r3;
                ldsm4t(smem_u32(Wl + r * WPAD + c), r0, r1, r2, r3);
                bl[2*np][0]=r0; bl[2*np][1]=r1; bl[2*np+1][0]=r2; bl[2*np+1][1]=r3;
            }
            #pragma unroll
            for (int mt = 0; mt < 2; mt++)
                #pragma unroll
                for (int nt = 0; nt < 8; nt++) {
                    mma_bf16(acc[mt][nt], ah[mt], bh[nt]);
                    mma_bf16(acc[mt][nt], ah[mt], bl[nt]);
                    mma_bf16(acc[mt][nt], al[mt], bh[nt]);
                }
        }
        __syncthreads();
    }

    #pragma unroll
    for (int mt = 0; mt < 2; mt++)
        #pragma unroll
        for (int nt = 0; nt < 8; nt++) {
            int row = rowBase + wm * 32 + mt * 16 + (lane >> 2);
            int col = colBase + wn * 64 + nt * 8 + 2 * (lane & 3);
            float b0 = bias[col], b1 = bias[col + 1];
            float v00 = (acc[mt][nt][0] + b0) * scale;
            float v01 = (acc[mt][nt][1] + b1) * scale;
            float v10 = (acc[mt][nt][2] + b0) * scale;
            float v11 = (acc[mt][nt][3] + b1) * scale;
            size_t i0 = (size_t)row * N + col;
            size_t i1 = (size_t)(row + 8) * N + col;
            if (SPLIT) {
                __nv_bfloat16 h, l;
                split2(v00, h, l); Chi[i0]     = h; Clo[i0]     = l;
                split2(v01, h, l); Chi[i0 + 1] = h; Clo[i0 + 1] = l;
                split2(v10, h, l); Chi[i1]     = h; Clo[i1]     = l;
                split2(v11, h, l); Chi[i1 + 1] = h; Clo[i1 + 1] = l;
            } else {
                Cf[i0] = v00; Cf[i0 + 1] = v01;
                Cf[i1] = v10; Cf[i1 + 1] = v11;
            }
        }
}

// ---------------------------------------------------------------------------
// Attention v2 (validated R6): register-direct P, 2 syncs/iter, 2 CTAs/SM.
// ---------------------------------------------------------------------------
#define ANT 128
#define AKT 64
#define APITCH 72
#define Q_EL (ANT*APITCH)            // 9216
#define KV_ARR (AKT*APITCH)          // 4608
#define KV_STAGE (4*KV_ARR)          // 18432
#define ATTN_SMEM ((2*Q_EL + 2*KV_STAGE) * 2)

__global__ __launch_bounds__(256, 2) void attn_mma()
{
    extern __shared__ __nv_bfloat16 smb[];
    __nv_bfloat16* Qh = smb;
    __nv_bfloat16* Ql = Qh + Q_EL;
    __nv_bfloat16* KV = Ql + Q_EL;          // stage s at KV + s*KV_STAGE

    const int tid = threadIdx.x, wid = tid >> 5, lane = tid & 31;
    const int b = blockIdx.x >> 4, h = blockIdx.x & 15;
    const int n0 = blockIdx.y * ANT;

    auto loadKV = [&](int kc0, int s) {
        __nv_bfloat16* base = KV + s * KV_STAGE;
        #pragma unroll
        for (int i = 0; i < 2; i++) {
            int t = tid + i * 256;
            int r = t >> 3, ch = t & 7;
            size_t gk = (size_t)(b * KC + kc0 + r) * (2 * DD) + h * HD + ch * 8;
            cpa16(base +            r * APITCH + ch * 8, g_kv_hi + gk);
            cpa16(base + KV_ARR   + r * APITCH + ch * 8, g_kv_lo + gk);
            cpa16(base + 2*KV_ARR + r * APITCH + ch * 8, g_kv_hi + gk + DD);
            cpa16(base + 3*KV_ARR + r * APITCH + ch * 8, g_kv_lo + gk + DD);
        }
        asm volatile("cp.async.commit_group;\n");
    };

    // Q via cp.async (folded into group 0 with first KV tile)
    #pragma unroll
    for (int i = 0; i < 4; i++) {
        int t = tid + i * 256;
        int r = t >> 3, ch = t & 7;
        size_t g = (size_t)(b * NN + n0 + r) * DD + h * HD + ch * 8;
        cpa16(Qh + r * APITCH + ch * 8, g_q_hi + g);
        cpa16(Ql + r * APITCH + ch * 8, g_q_lo + g);
    }
    loadKV(0, 0);        // group 0 (Q + KV tile 0)
    loadKV(AKT, 1);      // group 1

    float oacc[8][4];
    #pragma unroll
    for (int nt = 0; nt < 8; nt++)
        #pragma unroll
        for (int e = 0; e < 4; e++) oacc[nt][e] = 0.f;
    float d0 = 0.f, d1 = 0.f;   // per-thread partial row sums (rows r, r+8)

    const int NIT = KC / AKT;   // 32
    for (int it = 0; it < NIT; it++) {
        const int s = it & 1;
        __nv_bfloat16* Kh = KV + s * KV_STAGE;
        __nv_bfloat16* Kl = Kh + KV_ARR;
        __nv_bfloat16* Vh = Kh + 2*KV_ARR;
        __nv_bfloat16* Vl = Kh + 3*KV_ARR;

        if (it + 1 < NIT) asm volatile("cp.async.wait_group 1;\n");
        else              asm volatile("cp.async.wait_group 0;\n");
        __syncthreads();   // (A) stage s data visible

        // ---- S = Q @ K^T ----
        float sacc[8][4];
        #pragma unroll
        for (int nt = 0; nt < 8; nt++)
            #pragma unroll
            for (int e = 0; e < 4; e++) sacc[nt][e] = 0.f;

        #pragma unroll
        for (int d16 = 0; d16 < 4; d16++) {
            const int dd0 = d16 * 16;
            uint32_t ah[4], al[4];
            {
                int r = wid * 16 + (lane & 7) + ((lane >> 3) & 1) * 8;
                int c = dd0 + (lane >> 4) * 8;
                ldsm4(smem_u32(Qh + r * APITCH + c), ah[0], ah[1], ah[2], ah[3]);
                ldsm4(smem_u32(Ql + r * APITCH + c), al[0], al[1], al[2], al[3]);
            }
            uint32_t bh[8][2], bl[8][2];
            #pragma unroll
            for (int np = 0; np < 4; np++) {
                int r = np * 16 + (lane & 7) + ((lane >> 4)) * 8;
                int c = dd0 + ((lane >> 3) & 1) * 8;
                uint32_t r0, r1, r2, r3;
                ldsm4(smem_u32(Kh + r * APITCH + c), r0, r1, r2, r3);
                bh[2*np][0]=r0; bh[2*np][1]=r1; bh[2*np+1][0]=r2; bh[2*np+1][1]=r3;
                ldsm4(smem_u32(Kl + r * APITCH + c), r0, r1, r2, r3);
                bl[2*np][0]=r0; bl[2*np][1]=r1; bl[2*np+1][0]=r2; bl[2*np+1][1]=r3;
            }
            #pragma unroll
            for (int nt = 0; nt < 8; nt++) {
                mma_bf16(sacc[nt], ah, bh[nt]);
                mma_bf16(sacc[nt], ah, bl[nt]);
                mma_bf16(sacc[nt], al, bh[nt]);
            }
        }

        // ---- P = exp(clip(S)) in registers + partial row sums ----
        #pragma unroll
        for (int nt = 0; nt < 8; nt++) {
            #pragma unroll
            for (int e = 0; e < 4; e++)
                sacc[nt][e] = __expf(fminf(fmaxf(sacc[nt][e], -10.f), 10.f));
            d0 += sacc[nt][0] + sacc[nt][1];
            d1 += sacc[nt][2] + sacc[nt][3];
        }

        // ---- O += P @ V : accumulator fragments ARE the PV A-fragments ----
        #pragma unroll
        for (int c16 = 0; c16 < 4; c16++) {
            const int kk = c16 * 16;
            uint32_t ah[4], al[4];
            {
                const float* t0 = sacc[2*c16];
                const float* t1 = sacc[2*c16 + 1];
                __nv_bfloat162 h;
                h = __floats2bfloat162_rn(t0[0], t0[1]);
                ah[0] = *reinterpret_cast<uint32_t*>(&h);
                al[0] = packbf(t0[0] - __bfloat162float(h.x), t0[1] - __bfloat162float(h.y));
                h = __floats2bfloat162_rn(t0[2], t0[3]);
                ah[1] = *reinterpret_cast<uint32_t*>(&h);
                al[1] = packbf(t0[2] - __bfloat162float(h.x), t0[3] - __bfloat162float(h.y));
                h = __floats2bfloat162_rn(t1[0], t1[1]);
                ah[2] = *reinterpret_cast<uint32_t*>(&h);
                al[2] = packbf(t1[0] - __bfloat162float(h.x), t1[1] - __bfloat162float(h.y));
                h = __floats2bfloat162_rn(t1[2], t1[3]);
                ah[3] = *reinterpret_cast<uint32_t*>(&h);
                al[3] = packbf(t1[2] - __bfloat162float(h.x), t1[3] - __bfloat162float(h.y));
            }
            uint32_t bh[8][2], bl[8][2];
            #pragma unroll
            for (int np = 0; np < 4; np++) {
                int rv = kk + (lane & 7) + ((lane >> 3) & 1) * 8;
                int cv = np * 16 + (lane >> 4) * 8;
                uint32_t r0, r1, r2, r3;
                ldsm4t(smem_u32(Vh + rv * APITCH + cv), r0, r1, r2, r3);
                bh[2*np][0]=r0; bh[2*np][1]=r1; bh[2*np+1][0]=r2; bh[2*np+1][1]=r3;
                ldsm4t(smem_u32(Vl + rv * APITCH + cv), r0, r1, r2, r3);
                bl[2*np][0]=r0; bl[2*np][1]=r1; bl[2*np+1][0]=r2; bl[2*np+1][1]=r3;
            }
            #pragma unroll
            for (int nt = 0; nt < 8; nt++) {
                mma_bf16(oacc[nt], ah, bh[nt]);
                mma_bf16(oacc[nt], ah, bl[nt]);
                mma_bf16(oacc[nt], al, bh[nt]);
            }
        }
        __syncthreads();   // (B) stage s fully consumed
        if (it + 2 < NIT) loadKV((it + 2) * AKT, s);
    }

    // reduce row sums across the quad
    d0 += __shfl_xor_sync(0xffffffffu, d0, 1);
    d0 += __shfl_xor_sync(0xffffffffu, d0, 2);
    d1 += __shfl_xor_sync(0xffffffffu, d1, 1);
    d1 += __shfl_xor_sync(0xffffffffu, d1, 2);
    const float inv0 = 1.0f / d0;
    const float inv1 = 1.0f / d1;

    // normalize + write split output
    const int r0 = wid * 16 + (lane >> 2);
    #pragma unroll
    for (int nt = 0; nt < 8; nt++) {
        int c = nt * 8 + 2 * (lane & 3);
        size_t i0 = (size_t)(b * NN + n0 + r0) * DD + h * HD + c;
        size_t i1 = (size_t)(b * NN + n0 + r0 + 8) * DD + h * HD + c;
        __nv_bfloat16 hh, ll;
        split2(oacc[nt][0] * inv0, hh, ll); g_ao_hi[i0]     = hh; g_ao_lo[i0]     = ll;
        split2(oacc[nt][1] * inv0, hh, ll); g_ao_hi[i0 + 1] = hh; g_ao_lo[i0 + 1] = ll;
        split2(oacc[nt][2] * inv1, hh, ll); g_ao_hi[i1]     = hh; g_ao_lo[i1]     = ll;
        split2(oacc[nt][3] * inv1, hh, ll); g_ao_hi[i1 + 1] = hh; g_ao_lo[i1 + 1] = ll;
    }
}

// ---------------------------------------------------------------------------
__global__ void finalize_mean(float* out, int out_size)
{
    const int base = BB * NN * DD;
    for (int i = base + threadIdx.x; i < out_size; i += blockDim.x)
        out[i] = 1.0f / (float)KC;
}

// ---------------------------------------------------------------------------
extern "C" void kernel_launch(void* const* d_in, const int* in_sizes, int n_in,
                              void* d_out, int out_size)
{
    const float* x      = (const float*)d_in[0];
    const float* ctx    = (const float*)d_in[1];
    const float* q_w    = (const float*)d_in[2];
    const float* q_b    = (const float*)d_in[3];
    const float* kv_w   = (const float*)d_in[4];
    const float* kv_b   = (const float*)d_in[5];
    const float* proj_w = (const float*)d_in[6];
    const float* proj_b = (const float*)d_in[7];
    float* out = (float*)d_out;

    __nv_bfloat16 *xh,*xl,*qwh,*qwl,*kvwh,*kvwl,*pwh,*pwl,*cnh,*cnl,*qh,*ql,*kvh,*kvl,*aoh,*aol;
    cudaGetSymbolAddress((void**)&xh,  g_x_hi);  cudaGetSymbolAddress((void**)&xl,  g_x_lo);
    cudaGetSymbolAddress((void**)&qwh, g_qw_hi); cudaGetSymbolAddress((void**)&qwl, g_qw_lo);
    cudaGetSymbolAddress((void**)&kvwh,g_kvw_hi);cudaGetSymbolAddress((void**)&kvwl,g_kvw_lo);
    cudaGetSymbolAddress((void**)&pwh, g_pw_hi); cudaGetSymbolAddress((void**)&pwl, g_pw_lo);
    cudaGetSymbolAddress((void**)&cnh, g_cn_hi); cudaGetSymbolAddress((void**)&cnl, g_cn_lo);
    cudaGetSymbolAddress((void**)&qh,  g_q_hi);  cudaGetSymbolAddress((void**)&ql,  g_q_lo);
    cudaGetSymbolAddress((void**)&kvh, g_kv_hi); cudaGetSymbolAddress((void**)&kvl, g_kv_lo);
    cudaGetSymbolAddress((void**)&aoh, g_ao_hi); cudaGetSymbolAddress((void**)&aol, g_ao_lo);

    cudaFuncSetAttribute(mmgemm<true>,  cudaFuncAttributeMaxDynamicSharedMemorySize, GEMM_SMEM);
    cudaFuncSetAttribute(mmgemm<false>, cudaFuncAttributeMaxDynamicSharedMemorySize, GEMM_SMEM);
    cudaFuncSetAttribute(attn_mma,      cudaFuncAttributeMaxDynamicSharedMemorySize, ATTN_SMEM);

    split_kernel<<<(BB*NN*DD/4 + 255)/256, 256>>>(x, xh, xl, BB*NN*DD);
    split_kernel<<<(DD*DD/4 + 255)/256, 256>>>(q_w, qwh, qwl, DD*DD);
    split_kernel<<<(DD*2*DD/4 + 255)/256, 256>>>(kv_w, kvwh, kvwl, DD*2*DD);
    split_kernel<<<(DD*DD/4 + 255)/256, 256>>>(proj_w, pwh, pwl, DD*DD);

    rmsnorm_split<<<BB*KC, 256>>>(ctx);

    // q = (x @ q_w + q_b) * 0.125  -> split
    mmgemm<true><<<dim3(DD/GBN, BB*NN/GBM), 256, GEMM_SMEM>>>(
        xh, xl, qwh, qwl, q_b, 0.125f, nullptr, qh, ql, BB*NN, DD, DD);

    // kv = ctxn @ kv_w + kv_b  -> split
    mmgemm<true><<<dim3(2*DD/GBN, BB*KC/GBM), 256, GEMM_SMEM>>>(
        cnh, cnl, kvwh, kvwl, kv_b, 1.0f, nullptr, kvh, kvl, BB*KC, 2*DD, DD);

    // attention
    attn_mma<<<dim3(BB*HH, NN/ANT), 256, ATTN_SMEM>>>();

    // out = attn @ proj_w + proj_b (fp32)
    mmgemm<false><<<dim3(DD/GBN, BB*NN/GBM), 256, GEMM_SMEM>>>(
        aoh, aol, pwh, pwl, proj_b, 1.0f, out, nullptr, nullptr, BB*NN, DD, DD);

    if (out_size > BB * NN * DD)
        finalize_mean<<<1, 32>>>(out, out_size);
}

// round 8
// speedup vs baseline: 1.3737x; 1.1294x over previous
#include <cuda_runtime.h>
#include <cuda_bf16.h>
#include <cstdint>

#define BB 4
#define NN 2048
#define KC 2048
#define DD 1024
#define HH 16
#define HD 64
#define RMS_EPS 1e-6f

// ---------------------------------------------------------------------------
// Scratch (bf16 hi/lo split arrays)
// ---------------------------------------------------------------------------
__device__ __nv_bfloat16 g_x_hi[BB*NN*DD],   g_x_lo[BB*NN*DD];
__device__ __nv_bfloat16 g_qw_hi[DD*DD],     g_qw_lo[DD*DD];
__device__ __nv_bfloat16 g_kvw_hi[DD*2*DD],  g_kvw_lo[DD*2*DD];
__device__ __nv_bfloat16 g_pw_hi[DD*DD],     g_pw_lo[DD*DD];
__device__ __nv_bfloat16 g_cn_hi[BB*KC*DD],  g_cn_lo[BB*KC*DD];
__device__ __nv_bfloat16 g_q_hi[BB*NN*DD],   g_q_lo[BB*NN*DD];      // pre-scaled 0.125
__device__ __nv_bfloat16 g_kv_hi[BB*KC*2*DD],g_kv_lo[BB*KC*2*DD];
__device__ __nv_bfloat16 g_ao_hi[BB*NN*DD],  g_ao_lo[BB*NN*DD];

// ---------------------------------------------------------------------------
// PTX helpers
// ---------------------------------------------------------------------------
__device__ __forceinline__ uint32_t smem_u32(const void* p) {
    return (uint32_t)__cvta_generic_to_shared(p);
}
__device__ __forceinline__ void ldsm4(uint32_t a, uint32_t& r0, uint32_t& r1,
                                      uint32_t& r2, uint32_t& r3) {
    asm volatile("ldmatrix.sync.aligned.m8n8.x4.shared.b16 {%0,%1,%2,%3}, [%4];"
                 : "=r"(r0), "=r"(r1), "=r"(r2), "=r"(r3) : "r"(a));
}
__device__ __forceinline__ void ldsm4t(uint32_t a, uint32_t& r0, uint32_t& r1,
                                       uint32_t& r2, uint32_t& r3) {
    asm volatile("ldmatrix.sync.aligned.m8n8.x4.trans.shared.b16 {%0,%1,%2,%3}, [%4];"
                 : "=r"(r0), "=r"(r1), "=r"(r2), "=r"(r3) : "r"(a));
}
__device__ __forceinline__ void mma_bf16(float* c, const uint32_t* a, const uint32_t* b) {
    asm volatile(
        "mma.sync.aligned.m16n8k16.row.col.f32.bf16.bf16.f32 "
        "{%0,%1,%2,%3},{%4,%5,%6,%7},{%8,%9},{%0,%1,%2,%3};\n"
        : "+f"(c[0]), "+f"(c[1]), "+f"(c[2]), "+f"(c[3])
        : "r"(a[0]), "r"(a[1]), "r"(a[2]), "r"(a[3]), "r"(b[0]), "r"(b[1]));
}
__device__ __forceinline__ void cpa16(void* dst, const void* src) {
    uint32_t d = smem_u32(dst);
    asm volatile("cp.async.cg.shared.global [%0], [%1], 16;\n" :: "r"(d), "l"(src));
}
__device__ __forceinline__ void split2(float v, __nv_bfloat16& h, __nv_bfloat16& l) {
    h = __float2bfloat16(v);
    l = __float2bfloat16(v - __bfloat162float(h));
}
__device__ __forceinline__ uint32_t packbf(float x, float y) {
    __nv_bfloat162 t = __floats2bfloat162_rn(x, y);   // .x = x in low half
    return *reinterpret_cast<uint32_t*>(&t);
}
// pack hi parts of (x,y) and lo parts of (x,y) into two u32s
__device__ __forceinline__ void packsplit(float x, float y, uint32_t& hi, uint32_t& lo) {
    __nv_bfloat162 h = __floats2bfloat162_rn(x, y);
    hi = *reinterpret_cast<uint32_t*>(&h);
    lo = packbf(x - __bfloat162float(h.x), y - __bfloat162float(h.y));
}

// ---------------------------------------------------------------------------
// fp32 -> bf16 hi/lo split
// ---------------------------------------------------------------------------
__global__ __launch_bounds__(256) void split_kernel(const float* __restrict__ src,
                                                    __nv_bfloat16* __restrict__ hi,
                                                    __nv_bfloat16* __restrict__ lo, int n)
{
    int i = (blockIdx.x * 256 + threadIdx.x) * 4;
    if (i >= n) return;
    float4 v = *reinterpret_cast<const float4*>(src + i);
    uint32_t h0, l0, h1, l1;
    packsplit(v.x, v.y, h0, l0);
    packsplit(v.z, v.w, h1, l1);
    *reinterpret_cast<uint2*>(hi + i) = make_uint2(h0, h1);
    *reinterpret_cast<uint2*>(lo + i) = make_uint2(l0, l1);
}

// ---------------------------------------------------------------------------
// RMSNorm -> bf16 hi/lo
// ---------------------------------------------------------------------------
__global__ __launch_bounds__(256) void rmsnorm_split(const float* __restrict__ ctx)
{
    const int row = blockIdx.x;
    float4 v = reinterpret_cast<const float4*>(ctx + (size_t)row * DD)[threadIdx.x];
    float s = v.x*v.x + v.y*v.y + v.z*v.z + v.w*v.w;
    #pragma unroll
    for (int o = 16; o > 0; o >>= 1) s += __shfl_xor_sync(0xffffffffu, s, o);
    __shared__ float ws[8];
    if ((threadIdx.x & 31) == 0) ws[threadIdx.x >> 5] = s;
    __syncthreads();
    float tot = 0.f;
    #pragma unroll
    for (int i = 0; i < 8; i++) tot += ws[i];
    const float r = rsqrtf(tot * (1.0f / (float)DD) + RMS_EPS);
    const size_t base = (size_t)row * DD + threadIdx.x * 4;
    uint32_t h0, l0, h1, l1;
    packsplit(v.x * r, v.y * r, h0, l0);
    packsplit(v.z * r, v.w * r, h1, l1);
    *reinterpret_cast<uint2*>(g_cn_hi + base) = make_uint2(h0, h1);
    *reinterpret_cast<uint2*>(g_cn_lo + base) = make_uint2(l0, l1);
}

// ---------------------------------------------------------------------------
// Split-bf16 GEMM body: C = (Ahi+Alo)@(Whi+Wlo) + bias
// tile 128x128x32, 256 threads, 3-stage cp.async pipeline (1 sync/iter).
// ---------------------------------------------------------------------------
#define GBM 128
#define GBN 128
#define GBK 32
#define APAD 40
#define WPAD 136
#define A_EL (GBM*APAD)
#define W_EL (GBK*WPAD)
#define STG_EL (2*A_EL + 2*W_EL)              // 18944 elements = 37888 B
#define GEMM_SMEM (3*STG_EL*2)                // 113664 B

template<bool SPLIT>
__device__ __forceinline__ void gemm_body(
    __nv_bfloat16* sm,
    const __nv_bfloat16* __restrict__ Ahi, const __nv_bfloat16* __restrict__ Alo,
    const __nv_bfloat16* __restrict__ Whi, const __nv_bfloat16* __restrict__ Wlo,
    const float* __restrict__ bias, float scale,
    float* __restrict__ Cf, __nv_bfloat16* __restrict__ Chi, __nv_bfloat16* __restrict__ Clo,
    int rowBase, int colBase, int N, int K)
{
    const int tid = threadIdx.x;
    const int wid = tid >> 5, lane = tid & 31;
    const int wm = wid & 3;
    const int wn = wid >> 2;

    auto loadStage = [&](int kc, int s) {
        const int k0 = kc * GBK;
        __nv_bfloat16* Ah = sm + s * STG_EL;
        __nv_bfloat16* Al = Ah + A_EL;
        __nv_bfloat16* Wh = Al + A_EL;
        __nv_bfloat16* Wl = Wh + W_EL;
        #pragma unroll
        for (int i = 0; i < 2; i++) {
            int t = tid + i * 256;
            int r = t >> 2, ch = t & 3;
            size_t ga = (size_t)(rowBase + r) * K + k0 + ch * 8;
            cpa16(Ah + r * APAD + ch * 8, Ahi + ga);
            cpa16(Al + r * APAD + ch * 8, Alo + ga);
            int rw = t >> 4, cw = t & 15;
            size_t gw = (size_t)(k0 + rw) * N + colBase + cw * 8;
            cpa16(Wh + rw * WPAD + cw * 8, Whi + gw);
            cpa16(Wl + rw * WPAD + cw * 8, Wlo + gw);
        }
        asm volatile("cp.async.commit_group;\n");
    };

    float acc[2][8][4];
    #pragma unroll
    for (int mt = 0; mt < 2; mt++)
        #pragma unroll
        for (int nt = 0; nt < 8; nt++)
            #pragma unroll
            for (int e = 0; e < 4; e++) acc[mt][nt][e] = 0.f;

    const int NK = K / GBK;
    loadStage(0, 0);
    loadStage(1, 1);
    for (int kc = 0; kc < NK; kc++) {
        if (kc + 1 < NK) asm volatile("cp.async.wait_group 1;\n");
        else             asm volatile("cp.async.wait_group 0;\n");
        __syncthreads();                       // stage kc ready; stage (kc-1) drained
        if (kc + 2 < NK) loadStage(kc + 2, (kc + 2) % 3);

        __nv_bfloat16* Ah = sm + (kc % 3) * STG_EL;
        __nv_bfloat16* Al = Ah + A_EL;
        __nv_bfloat16* Wh = Al + A_EL;
        __nv_bfloat16* Wl = Wh + W_EL;

        #pragma unroll
        for (int k16 = 0; k16 < 2; k16++) {
            const int kk = k16 * 16;
            uint32_t ah[2][4], al[2][4];
            #pragma unroll
            for (int mt = 0; mt < 2; mt++) {
                int r = wm * 32 + mt * 16 + (lane & 7) + ((lane >> 3) & 1) * 8;
                int c = kk + (lane >> 4) * 8;
                ldsm4(smem_u32(Ah + r * APAD + c), ah[mt][0], ah[mt][1], ah[mt][2], ah[mt][3]);
                ldsm4(smem_u32(Al + r * APAD + c), al[mt][0], al[mt][1], al[mt][2], al[mt][3]);
            }
            uint32_t bh[8][2], bl[8][2];
            #pragma unroll
            for (int np = 0; np < 4; np++) {
                int r = kk + (lane & 7) + ((lane >> 3) & 1) * 8;
                int c = wn * 64 + np * 16 + (lane >> 4) * 8;
                uint32_t r0, r1, r2, r3;
                ldsm4t(smem_u32(Wh + r * WPAD + c), r0, r1, r2, r3);
                bh[2*np][0]=r0; bh[2*np][1]=r1; bh[2*np+1][0]=r2; bh[2*np+1][1]=r3;
                ldsm4t(smem_u32(Wl + r * WPAD + c), r0, r1, r2, r3);
                bl[2*np][0]=r0; bl[2*np][1]=r1; bl[2*np+1][0]=r2; bl[2*np+1][1]=r3;
            }
            #pragma unroll
            for (int mt = 0; mt < 2; mt++)
                #pragma unroll
                for (int nt = 0; nt < 8; nt++) {
                    mma_bf16(acc[mt][nt], ah[mt], bh[nt]);
                    mma_bf16(acc[mt][nt], ah[mt], bl[nt]);
                    mma_bf16(acc[mt][nt], al[mt], bh[nt]);
                }
        }
    }

    #pragma unroll
    for (int mt = 0; mt < 2; mt++)
        #pragma unroll
        for (int nt = 0; nt < 8; nt++) {
            int row = rowBase + wm * 32 + mt * 16 + (lane >> 2);
            int col = colBase + wn * 64 + nt * 8 + 2 * (lane & 3);
            float b0 = bias[col], b1 = bias[col + 1];
            float v00 = (acc[mt][nt][0] + b0) * scale;
            float v01 = (acc[mt][nt][1] + b1) * scale;
            float v10 = (acc[mt][nt][2] + b0) * scale;
            float v11 = (acc[mt][nt][3] + b1) * scale;
            size_t i0 = (size_t)row * N + col;
            size_t i1 = (size_t)(row + 8) * N + col;
            if (SPLIT) {
                uint32_t h, l;
                packsplit(v00, v01, h, l);
                *reinterpret_cast<uint32_t*>(Chi + i0) = h;
                *reinterpret_cast<uint32_t*>(Clo + i0) = l;
                packsplit(v10, v11, h, l);
                *reinterpret_cast<uint32_t*>(Chi + i1) = h;
                *reinterpret_cast<uint32_t*>(Clo + i1) = l;
            } else {
                *reinterpret_cast<float2*>(Cf + i0) = make_float2(v00, v01);
                *reinterpret_cast<float2*>(Cf + i1) = make_float2(v10, v11);
            }
        }
}

// Merged q + kv projection: grid.x in [0,24): 0-7 -> q (N=1024), 8-23 -> kv (N=2048)
__global__ __launch_bounds__(256, 2) void mmgemm_qkv(
    const float* __restrict__ q_b, const float* __restrict__ kv_b)
{
    extern __shared__ __nv_bfloat16 sm[];
    if (blockIdx.x < 8) {
        gemm_body<true>(sm, g_x_hi, g_x_lo, g_qw_hi, g_qw_lo, q_b, 0.125f,
                        nullptr, g_q_hi, g_q_lo,
                        blockIdx.y * GBM, blockIdx.x * GBN, DD, DD);
    } else {
        gemm_body<true>(sm, g_cn_hi, g_cn_lo, g_kvw_hi, g_kvw_lo, kv_b, 1.0f,
                        nullptr, g_kv_hi, g_kv_lo,
                        blockIdx.y * GBM, (blockIdx.x - 8) * GBN, 2 * DD, DD);
    }
}

// Output projection (fp32 out)
__global__ __launch_bounds__(256, 2) void mmgemm_proj(
    const float* __restrict__ proj_b, float* __restrict__ out)
{
    extern __shared__ __nv_bfloat16 sm[];
    gemm_body<false>(sm, g_ao_hi, g_ao_lo, g_pw_hi, g_pw_lo, proj_b, 1.0f,
                     out, nullptr, nullptr,
                     blockIdx.y * GBM, blockIdx.x * GBN, DD, DD);
}

// ---------------------------------------------------------------------------
// Attention v2 (validated R6/R7): register-direct P, 2 syncs/iter, 2 CTAs/SM.
// ---------------------------------------------------------------------------
#define ANT 128
#define AKT 64
#define APITCH 72
#define Q_EL (ANT*APITCH)            // 9216
#define KV_ARR (AKT*APITCH)          // 4608
#define KV_STAGE (4*KV_ARR)          // 18432
#define ATTN_SMEM ((2*Q_EL + 2*KV_STAGE) * 2)

__global__ __launch_bounds__(256, 2) void attn_mma()
{
    extern __shared__ __nv_bfloat16 smb[];
    __nv_bfloat16* Qh = smb;
    __nv_bfloat16* Ql = Qh + Q_EL;
    __nv_bfloat16* KV = Ql + Q_EL;          // stage s at KV + s*KV_STAGE

    const int tid = threadIdx.x, wid = tid >> 5, lane = tid & 31;
    const int b = blockIdx.x >> 4, h = blockIdx.x & 15;
    const int n0 = blockIdx.y * ANT;

    auto loadKV = [&](int kc0, int s) {
        __nv_bfloat16* base = KV + s * KV_STAGE;
        #pragma unroll
        for (int i = 0; i < 2; i++) {
            int t = tid + i * 256;
            int r = t >> 3, ch = t & 7;
            size_t gk = (size_t)(b * KC + kc0 + r) * (2 * DD) + h * HD + ch * 8;
            cpa16(base +            r * APITCH + ch * 8, g_kv_hi + gk);
            cpa16(base + KV_ARR   + r * APITCH + ch * 8, g_kv_lo + gk);
            cpa16(base + 2*KV_ARR + r * APITCH + ch * 8, g_kv_hi + gk + DD);
            cpa16(base + 3*KV_ARR + r * APITCH + ch * 8, g_kv_lo + gk + DD);
        }
        asm volatile("cp.async.commit_group;\n");
    };

    // Q via cp.async (folded into group 0 with first KV tile)
    #pragma unroll
    for (int i = 0; i < 4; i++) {
        int t = tid + i * 256;
        int r = t >> 3, ch = t & 7;
        size_t g = (size_t)(b * NN + n0 + r) * DD + h * HD + ch * 8;
        cpa16(Qh + r * APITCH + ch * 8, g_q_hi + g);
        cpa16(Ql + r * APITCH + ch * 8, g_q_lo + g);
    }
    loadKV(0, 0);        // group 0 (Q + KV tile 0)
    loadKV(AKT, 1);      // group 1

    float oacc[8][4];
    #pragma unroll
    for (int nt = 0; nt < 8; nt++)
        #pragma unroll
        for (int e = 0; e < 4; e++) oacc[nt][e] = 0.f;
    float d0 = 0.f, d1 = 0.f;   // per-thread partial row sums (rows r, r+8)

    const int NIT = KC / AKT;   // 32
    for (int it = 0; it < NIT; it++) {
        const int s = it & 1;
        __nv_bfloat16* Kh = KV + s * KV_STAGE;
        __nv_bfloat16* Kl = Kh + KV_ARR;
        __nv_bfloat16* Vh = Kh + 2*KV_ARR;
        __nv_bfloat16* Vl = Kh + 3*KV_ARR;

        if (it + 1 < NIT) asm volatile("cp.async.wait_group 1;\n");
        else              asm volatile("cp.async.wait_group 0;\n");
        __syncthreads();   // (A) stage s data visible

        // ---- S = Q @ K^T ----
        float sacc[8][4];
        #pragma unroll
        for (int nt = 0; nt < 8; nt++)
            #pragma unroll
            for (int e = 0; e < 4; e++) sacc[nt][e] = 0.f;

        #pragma unroll
        for (int d16 = 0; d16 < 4; d16++) {
            const int dd0 = d16 * 16;
            uint32_t ah[4], al[4];
            {
                int r = wid * 16 + (lane & 7) + ((lane >> 3) & 1) * 8;
                int c = dd0 + (lane >> 4) * 8;
                ldsm4(smem_u32(Qh + r * APITCH + c), ah[0], ah[1], ah[2], ah[3]);
                ldsm4(smem_u32(Ql + r * APITCH + c), al[0], al[1], al[2], al[3]);
            }
            uint32_t bh[8][2], bl[8][2];
            #pragma unroll
            for (int np = 0; np < 4; np++) {
                int r = np * 16 + (lane & 7) + ((lane >> 4)) * 8;
                int c = dd0 + ((lane >> 3) & 1) * 8;
                uint32_t r0, r1, r2, r3;
                ldsm4(smem_u32(Kh + r * APITCH + c), r0, r1, r2, r3);
                bh[2*np][0]=r0; bh[2*np][1]=r1; bh[2*np+1][0]=r2; bh[2*np+1][1]=r3;
                ldsm4(smem_u32(Kl + r * APITCH + c), r0, r1, r2, r3);
                bl[2*np][0]=r0; bl[2*np][1]=r1; bl[2*np+1][0]=r2; bl[2*np+1][1]=r3;
            }
            #pragma unroll
            for (int nt = 0; nt < 8; nt++) {
                mma_bf16(sacc[nt], ah, bh[nt]);
                mma_bf16(sacc[nt], ah, bl[nt]);
                mma_bf16(sacc[nt], al, bh[nt]);
            }
        }

        // ---- P = exp(clip(S)) in registers + partial row sums ----
        #pragma unroll
        for (int nt = 0; nt < 8; nt++) {
            #pragma unroll
            for (int e = 0; e < 4; e++)
                sacc[nt][e] = __expf(fminf(fmaxf(sacc[nt][e], -10.f), 10.f));
            d0 += sacc[nt][0] + sacc[nt][1];
            d1 += sacc[nt][2] + sacc[nt][3];
        }

        // ---- O += P @ V : accumulator fragments ARE the PV A-fragments ----
        #pragma unroll
        for (int c16 = 0; c16 < 4; c16++) {
            const int kk = c16 * 16;
            uint32_t ah[4], al[4];
            {
                const float* t0 = sacc[2*c16];
                const float* t1 = sacc[2*c16 + 1];
                packsplit(t0[0], t0[1], ah[0], al[0]);
                packsplit(t0[2], t0[3], ah[1], al[1]);
                packsplit(t1[0], t1[1], ah[2], al[2]);
                packsplit(t1[2], t1[3], ah[3], al[3]);
            }
            uint32_t bh[8][2], bl[8][2];
            #pragma unroll
            for (int np = 0; np < 4; np++) {
                int rv = kk + (lane & 7) + ((lane >> 3) & 1) * 8;
                int cv = np * 16 + (lane >> 4) * 8;
                uint32_t r0, r1, r2, r3;
                ldsm4t(smem_u32(Vh + rv * APITCH + cv), r0, r1, r2, r3);
                bh[2*np][0]=r0; bh[2*np][1]=r1; bh[2*np+1][0]=r2; bh[2*np+1][1]=r3;
                ldsm4t(smem_u32(Vl + rv * APITCH + cv), r0, r1, r2, r3);
                bl[2*np][0]=r0; bl[2*np][1]=r1; bl[2*np+1][0]=r2; bl[2*np+1][1]=r3;
            }
            #pragma unroll
            for (int nt = 0; nt < 8; nt++) {
                mma_bf16(oacc[nt], ah, bh[nt]);
                mma_bf16(oacc[nt], ah, bl[nt]);
                mma_bf16(oacc[nt], al, bh[nt]);
            }
        }
        __syncthreads();   // (B) stage s fully consumed
        if (it + 2 < NIT) loadKV((it + 2) * AKT, s);
    }

    // reduce row sums across the quad
    d0 += __shfl_xor_sync(0xffffffffu, d0, 1);
    d0 += __shfl_xor_sync(0xffffffffu, d0, 2);
    d1 += __shfl_xor_sync(0xffffffffu, d1, 1);
    d1 += __shfl_xor_sync(0xffffffffu, d1, 2);
    const float inv0 = 1.0f / d0;
    const float inv1 = 1.0f / d1;

    // normalize + write split output (packed u32 stores)
    const int r0 = wid * 16 + (lane >> 2);
    #pragma unroll
    for (int nt = 0; nt < 8; nt++) {
        int c = nt * 8 + 2 * (lane & 3);
        size_t i0 = (size_t)(b * NN + n0 + r0) * DD + h * HD + c;
        size_t i1 = (size_t)(b * NN + n0 + r0 + 8) * DD + h * HD + c;
        uint32_t hh, ll;
        packsplit(oacc[nt][0] * inv0, oacc[nt][1] * inv0, hh, ll);
        *reinterpret_cast<uint32_t*>(g_ao_hi + i0) = hh;
        *reinterpret_cast<uint32_t*>(g_ao_lo + i0) = ll;
        packsplit(oacc[nt][2] * inv1, oacc[nt][3] * inv1, hh, ll);
        *reinterpret_cast<uint32_t*>(g_ao_hi + i1) = hh;
        *reinterpret_cast<uint32_t*>(g_ao_lo + i1) = ll;
    }
}

// ---------------------------------------------------------------------------
__global__ void finalize_mean(float* out, int out_size)
{
    const int base = BB * NN * DD;
    for (int i = base + threadIdx.x; i < out_size; i += blockDim.x)
        out[i] = 1.0f / (float)KC;
}

// ---------------------------------------------------------------------------
extern "C" void kernel_launch(void* const* d_in, const int* in_sizes, int n_in,
                              void* d_out, int out_size)
{
    const float* x      = (const float*)d_in[0];
    const float* ctx    = (const float*)d_in[1];
    const float* q_w    = (const float*)d_in[2];
    const float* q_b    = (const float*)d_in[3];
    const float* kv_w   = (const float*)d_in[4];
    const float* kv_b   = (const float*)d_in[5];
    const float* proj_w = (const float*)d_in[6];
    const float* proj_b = (const float*)d_in[7];
    float* out = (float*)d_out;

    __nv_bfloat16 *xh,*xl,*qwh,*qwl,*kvwh,*kvwl,*pwh,*pwl;
    cudaGetSymbolAddress((void**)&xh,  g_x_hi);  cudaGetSymbolAddress((void**)&xl,  g_x_lo);
    cudaGetSymbolAddress((void**)&qwh, g_qw_hi); cudaGetSymbolAddress((void**)&qwl, g_qw_lo);
    cudaGetSymbolAddress((void**)&kvwh,g_kvw_hi);cudaGetSymbolAddress((void**)&kvwl,g_kvw_lo);
    cudaGetSymbolAddress((void**)&pwh, g_pw_hi); cudaGetSymbolAddress((void**)&pwl, g_pw_lo);

    cudaFuncSetAttribute(mmgemm_qkv,  cudaFuncAttributeMaxDynamicSharedMemorySize, GEMM_SMEM);
    cudaFuncSetAttribute(mmgemm_proj, cudaFuncAttributeMaxDynamicSharedMemorySize, GEMM_SMEM);
    cudaFuncSetAttribute(attn_mma,    cudaFuncAttributeMaxDynamicSharedMemorySize, ATTN_SMEM);

    split_kernel<<<(BB*NN*DD/4 + 255)/256, 256>>>(x, xh, xl, BB*NN*DD);
    split_kernel<<<(DD*DD/4 + 255)/256, 256>>>(q_w, qwh, qwl, DD*DD);
    split_kernel<<<(DD*2*DD/4 + 255)/256, 256>>>(kv_w, kvwh, kvwl, DD*2*DD);
    split_kernel<<<(DD*DD/4 + 255)/256, 256>>>(proj_w, pwh, pwl, DD*DD);

    rmsnorm_split<<<BB*KC, 256>>>(ctx);

    // q and kv projections merged into one launch
    mmgemm_qkv<<<dim3(24, BB*NN/GBM), 256, GEMM_SMEM>>>(q_b, kv_b);

    // attention
    attn_mma<<<dim3(BB*HH, NN/ANT), 256, ATTN_SMEM>>>();

    // out = attn @ proj_w + proj_b (fp32)
    mmgemm_proj<<<dim3(DD/GBN, BB*NN/GBM), 256, GEMM_SMEM>>>(proj_b, out);

    if (out_size > BB * NN * DD)
        finalize_mean<<<1, 32>>>(out, out_size);
}

// round 10
// speedup vs baseline: 1.5775x; 1.1484x over previous
#include <cuda_runtime.h>
#include <cuda_bf16.h>
#include <cuda_fp16.h>
#include <cstdint>

#define BB 4
#define NN 2048
#define KC 2048
#define DD 1024
#define HH 16
#define HD 64
#define RMS_EPS 1e-6f

// ---------------------------------------------------------------------------
// Scratch
// ---------------------------------------------------------------------------
__device__ __nv_bfloat16 g_x_hi[BB*NN*DD],   g_x_lo[BB*NN*DD];
__device__ __nv_bfloat16 g_qw_hi[DD*DD],     g_qw_lo[DD*DD];
__device__ __nv_bfloat16 g_kvw_hi[DD*2*DD],  g_kvw_lo[DD*2*DD];
__device__ __nv_bfloat16 g_pw_hi[DD*DD],     g_pw_lo[DD*DD];
__device__ __nv_bfloat16 g_cn_hi[BB*KC*DD],  g_cn_lo[BB*KC*DD];
__device__ __nv_bfloat16 g_ao_hi[BB*NN*DD],  g_ao_lo[BB*NN*DD];
__device__ __half        g_q_h[BB*NN*DD],    g_q_l[BB*NN*DD];     // fp16 split, pre-scaled 0.125
__device__ __half        g_kv_f[BB*KC*2*DD];                      // fp16 single

// ---------------------------------------------------------------------------
// PTX helpers
// ---------------------------------------------------------------------------
__device__ __forceinline__ uint32_t smem_u32(const void* p) {
    return (uint32_t)__cvta_generic_to_shared(p);
}
__device__ __forceinline__ void ldsm4(uint32_t a, uint32_t& r0, uint32_t& r1,
                                      uint32_t& r2, uint32_t& r3) {
    asm volatile("ldmatrix.sync.aligned.m8n8.x4.shared.b16 {%0,%1,%2,%3}, [%4];"
                 : "=r"(r0), "=r"(r1), "=r"(r2), "=r"(r3) : "r"(a));
}
__device__ __forceinline__ void ldsm4t(uint32_t a, uint32_t& r0, uint32_t& r1,
                                       uint32_t& r2, uint32_t& r3) {
    asm volatile("ldmatrix.sync.aligned.m8n8.x4.trans.shared.b16 {%0,%1,%2,%3}, [%4];"
                 : "=r"(r0), "=r"(r1), "=r"(r2), "=r"(r3) : "r"(a));
}
__device__ __forceinline__ void mma_bf16(float* c, const uint32_t* a, const uint32_t* b) {
    asm volatile(
        "mma.sync.aligned.m16n8k16.row.col.f32.bf16.bf16.f32 "
        "{%0,%1,%2,%3},{%4,%5,%6,%7},{%8,%9},{%0,%1,%2,%3};\n"
        : "+f"(c[0]), "+f"(c[1]), "+f"(c[2]), "+f"(c[3])
        : "r"(a[0]), "r"(a[1]), "r"(a[2]), "r"(a[3]), "r"(b[0]), "r"(b[1]));
}
__device__ __forceinline__ void mma_f16(float* c, const uint32_t* a, const uint32_t* b) {
    asm volatile(
        "mma.sync.aligned.m16n8k16.row.col.f32.f16.f16.f32 "
        "{%0,%1,%2,%3},{%4,%5,%6,%7},{%8,%9},{%0,%1,%2,%3};\n"
        : "+f"(c[0]), "+f"(c[1]), "+f"(c[2]), "+f"(c[3])
        : "r"(a[0]), "r"(a[1]), "r"(a[2]), "r"(a[3]), "r"(b[0]), "r"(b[1]));
}
__device__ __forceinline__ void cpa16(void* dst, const void* src) {
    uint32_t d = smem_u32(dst);
    asm volatile("cp.async.cg.shared.global [%0], [%1], 16;\n" :: "r"(d), "l"(src));
}
__device__ __forceinline__ uint32_t packbf(float x, float y) {
    __nv_bfloat162 t = __floats2bfloat162_rn(x, y);
    return *reinterpret_cast<uint32_t*>(&t);
}
__device__ __forceinline__ void packsplit(float x, float y, uint32_t& hi, uint32_t& lo) {
    __nv_bfloat162 h = __floats2bfloat162_rn(x, y);
    hi = *reinterpret_cast<uint32_t*>(&h);
    lo = packbf(x - __bfloat162float(h.x), y - __bfloat162float(h.y));
}
__device__ __forceinline__ uint32_t packh(float x, float y) {
    __half2 t = __floats2half2_rn(x, y);
    return *reinterpret_cast<uint32_t*>(&t);
}
__device__ __forceinline__ void packsplit_h(float x, float y, uint32_t& hi, uint32_t& lo) {
    __half hx = __float2half_rn(x), hy = __float2half_rn(y);
    __half2 hp = __halves2half2(hx, hy);
    hi = *reinterpret_cast<uint32_t*>(&hp);
    lo = packh(x - __half2float(hx), y - __half2float(hy));
}

// ---------------------------------------------------------------------------
// fp32 -> bf16 hi/lo split
// ---------------------------------------------------------------------------
__global__ __launch_bounds__(256) void split_kernel(const float* __restrict__ src,
                                                    __nv_bfloat16* __restrict__ hi,
                                                    __nv_bfloat16* __restrict__ lo, int n)
{
    int i = (blockIdx.x * 256 + threadIdx.x) * 4;
    if (i >= n) return;
    float4 v = *reinterpret_cast<const float4*>(src + i);
    uint32_t h0, l0, h1, l1;
    packsplit(v.x, v.y, h0, l0);
    packsplit(v.z, v.w, h1, l1);
    *reinterpret_cast<uint2*>(hi + i) = make_uint2(h0, h1);
    *reinterpret_cast<uint2*>(lo + i) = make_uint2(l0, l1);
}

// ---------------------------------------------------------------------------
// RMSNorm -> bf16 hi/lo
// ---------------------------------------------------------------------------
__global__ __launch_bounds__(256) void rmsnorm_split(const float* __restrict__ ctx)
{
    const int row = blockIdx.x;
    float4 v = reinterpret_cast<const float4*>(ctx + (size_t)row * DD)[threadIdx.x];
    float s = v.x*v.x + v.y*v.y + v.z*v.z + v.w*v.w;
    #pragma unroll
    for (int o = 16; o > 0; o >>= 1) s += __shfl_xor_sync(0xffffffffu, s, o);
    __shared__ float ws[8];
    if ((threadIdx.x & 31) == 0) ws[threadIdx.x >> 5] = s;
    __syncthreads();
    float tot = 0.f;
    #pragma unroll
    for (int i = 0; i < 8; i++) tot += ws[i];
    const float r = rsqrtf(tot * (1.0f / (float)DD) + RMS_EPS);
    const size_t base = (size_t)row * DD + threadIdx.x * 4;
    uint32_t h0, l0, h1, l1;
    packsplit(v.x * r, v.y * r, h0, l0);
    packsplit(v.z * r, v.w * r, h1, l1);
    *reinterpret_cast<uint2*>(g_cn_hi + base) = make_uint2(h0, h1);
    *reinterpret_cast<uint2*>(g_cn_lo + base) = make_uint2(l0, l1);
}

// ---------------------------------------------------------------------------
// Split-bf16 GEMM body (R8-validated): 128x128x32, 3-stage, 1 sync/iter.
// MODE: 0 = fp32 out, 2 = fp16 split out, 3 = fp16 single out
// ---------------------------------------------------------------------------
#define GBM 128
#define GBN 128
#define GBK 32
#define APAD 40
#define WPAD 136
#define A_EL (GBM*APAD)
#define W_EL (GBK*WPAD)
#define STG_EL (2*A_EL + 2*W_EL)
#define GEMM_SMEM (3*STG_EL*2)

template<int MODE>
__device__ __forceinline__ void gemm_body(
    __nv_bfloat16* sm,
    const __nv_bfloat16* __restrict__ Ahi, const __nv_bfloat16* __restrict__ Alo,
    const __nv_bfloat16* __restrict__ Whi, const __nv_bfloat16* __restrict__ Wlo,
    const float* __restrict__ bias, float scale,
    float* __restrict__ Cf, __half* __restrict__ H1, __half* __restrict__ H2,
    int rowBase, int colBase, int N, int K)
{
    const int tid = threadIdx.x;
    const int wid = tid >> 5, lane = tid & 31;
    const int wm = wid & 3;
    const int wn = wid >> 2;

    auto loadStage = [&](int kc, int s) {
        const int k0 = kc * GBK;
        __nv_bfloat16* Ah = sm + s * STG_EL;
        __nv_bfloat16* Al = Ah + A_EL;
        __nv_bfloat16* Wh = Al + A_EL;
        __nv_bfloat16* Wl = Wh + W_EL;
        #pragma unroll
        for (int i = 0; i < 2; i++) {
            int t = tid + i * 256;
            int r = t >> 2, ch = t & 3;
            size_t ga = (size_t)(rowBase + r) * K + k0 + ch * 8;
            cpa16(Ah + r * APAD + ch * 8, Ahi + ga);
            cpa16(Al + r * APAD + ch * 8, Alo + ga);
            int rw = t >> 4, cw = t & 15;
            size_t gw = (size_t)(k0 + rw) * N + colBase + cw * 8;
            cpa16(Wh + rw * WPAD + cw * 8, Whi + gw);
            cpa16(Wl + rw * WPAD + cw * 8, Wlo + gw);
        }
        asm volatile("cp.async.commit_group;\n");
    };

    float acc[2][8][4];
    #pragma unroll
    for (int mt = 0; mt < 2; mt++)
        #pragma unroll
        for (int nt = 0; nt < 8; nt++)
            #pragma unroll
            for (int e = 0; e < 4; e++) acc[mt][nt][e] = 0.f;

    const int NK = K / GBK;
    loadStage(0, 0);
    loadStage(1, 1);
    for (int kc = 0; kc < NK; kc++) {
        if (kc + 1 < NK) asm volatile("cp.async.wait_group 1;\n");
        else             asm volatile("cp.async.wait_group 0;\n");
        __syncthreads();
        if (kc + 2 < NK) loadStage(kc + 2, (kc + 2) % 3);

        __nv_bfloat16* Ah = sm + (kc % 3) * STG_EL;
        __nv_bfloat16* Al = Ah + A_EL;
        __nv_bfloat16* Wh = Al + A_EL;
        __nv_bfloat16* Wl = Wh + W_EL;

        #pragma unroll
        for (int k16 = 0; k16 < 2; k16++) {
            const int kk = k16 * 16;
            uint32_t ah[2][4], al[2][4];
            #pragma unroll
            for (int mt = 0; mt < 2; mt++) {
                int r = wm * 32 + mt * 16 + (lane & 7) + ((lane >> 3) & 1) * 8;
                int c = kk + (lane >> 4) * 8;
                ldsm4(smem_u32(Ah + r * APAD + c), ah[mt][0], ah[mt][1], ah[mt][2], ah[mt][3]);
                ldsm4(smem_u32(Al + r * APAD + c), al[mt][0], al[mt][1], al[mt][2], al[mt][3]);
            }
            uint32_t bh[8][2], bl[8][2];
            #pragma unroll
            for (int np = 0; np < 4; np++) {
                int r = kk + (lane & 7) + ((lane >> 3) & 1) * 8;
                int c = wn * 64 + np * 16 + (lane >> 4) * 8;
                uint32_t r0, r1, r2, r3;
                ldsm4t(smem_u32(Wh + r * WPAD + c), r0, r1, r2, r3);
                bh[2*np][0]=r0; bh[2*np][1]=r1; bh[2*np+1][0]=r2; bh[2*np+1][1]=r3;
                ldsm4t(smem_u32(Wl + r * WPAD + c), r0, r1, r2, r3);
                bl[2*np][0]=r0; bl[2*np][1]=r1; bl[2*np+1][0]=r2; bl[2*np+1][1]=r3;
            }
            #pragma unroll
            for (int mt = 0; mt < 2; mt++)
                #pragma unroll
                for (int nt = 0; nt < 8; nt++) {
                    mma_bf16(acc[mt][nt], ah[mt], bh[nt]);
                    mma_bf16(acc[mt][nt], ah[mt], bl[nt]);
                    mma_bf16(acc[mt][nt], al[mt], bh[nt]);
                }
        }
    }

    #pragma unroll
    for (int mt = 0; mt < 2; mt++)
        #pragma unroll
        for (int nt = 0; nt < 8; nt++) {
            int row = rowBase + wm * 32 + mt * 16 + (lane >> 2);
            int col = colBase + wn * 64 + nt * 8 + 2 * (lane & 3);
            float b0 = bias[col], b1 = bias[col + 1];
            float v00 = (acc[mt][nt][0] + b0) * scale;
            float v01 = (acc[mt][nt][1] + b1) * scale;
            float v10 = (acc[mt][nt][2] + b0) * scale;
            float v11 = (acc[mt][nt][3] + b1) * scale;
            size_t i0 = (size_t)row * N + col;
            size_t i1 = (size_t)(row + 8) * N + col;
            if (MODE == 0) {
                *reinterpret_cast<float2*>(Cf + i0) = make_float2(v00, v01);
                *reinterpret_cast<float2*>(Cf + i1) = make_float2(v10, v11);
            } else if (MODE == 2) {
                uint32_t h, l;
                packsplit_h(v00, v01, h, l);
                *reinterpret_cast<uint32_t*>(H1 + i0) = h;
                *reinterpret_cast<uint32_t*>(H2 + i0) = l;
                packsplit_h(v10, v11, h, l);
                *reinterpret_cast<uint32_t*>(H1 + i1) = h;
                *reinterpret_cast<uint32_t*>(H2 + i1) = l;
            } else {
                *reinterpret_cast<uint32_t*>(H1 + i0) = packh(v00, v01);
                *reinterpret_cast<uint32_t*>(H1 + i1) = packh(v10, v11);
            }
        }
}

// Merged q + kv projection: blocks 0-7 -> q (fp16 split), 8-23 -> kv (fp16)
__global__ __launch_bounds__(256, 2) void mmgemm_qkv(
    const float* __restrict__ q_b, const float* __restrict__ kv_b)
{
    extern __shared__ __nv_bfloat16 sm[];
    if (blockIdx.x < 8) {
        gemm_body<2>(sm, g_x_hi, g_x_lo, g_qw_hi, g_qw_lo, q_b, 0.125f,
                     nullptr, g_q_h, g_q_l,
                     blockIdx.y * GBM, blockIdx.x * GBN, DD, DD);
    } else {
        gemm_body<3>(sm, g_cn_hi, g_cn_lo, g_kvw_hi, g_kvw_lo, kv_b, 1.0f,
                     nullptr, g_kv_f, nullptr,
                     blockIdx.y * GBM, (blockIdx.x - 8) * GBN, 2 * DD, DD);
    }
}

__global__ __launch_bounds__(256, 2) void mmgemm_proj(
    const float* __restrict__ proj_b, float* __restrict__ out)
{
    extern __shared__ __nv_bfloat16 sm[];
    gemm_body<0>(sm, g_ao_hi, g_ao_lo, g_pw_hi, g_pw_lo, proj_b, 1.0f,
                 out, nullptr, nullptr,
                 blockIdx.y * GBM, blockIdx.x * GBN, DD, DD);
}

// ---------------------------------------------------------------------------
// Attention v3: fp16 2-term QK and PV, Q fragments in registers,
// 3-stage single-sync KV pipeline, 2 CTAs/SM.
// smem: Qh/Ql (fp16 128x72) + 3 stages of (K,V) fp16 64x72 = 92160 B
// ---------------------------------------------------------------------------
#define ANT 128
#define AKT 64
#define APITCH 72
#define Q_EL (ANT*APITCH)            // 9216 halves
#define KV_K (AKT*APITCH)            // 4608 halves per array
#define ATTN_SMEM ((2*Q_EL + 6*KV_K) * 2)

__global__ __launch_bounds__(256, 2) void attn_mma()
{
    extern __shared__ __half smh[];
    __half* Qh = smh;
    __half* Ql = Qh + Q_EL;
    __half* KV = Ql + Q_EL;          // stage s: K at KV + s*2*KV_K, V at +KV_K

    const int tid = threadIdx.x, wid = tid >> 5, lane = tid & 31;
    const int b = blockIdx.x >> 4, h = blockIdx.x & 15;
    const int n0 = blockIdx.y * ANT;

    auto loadKV = [&](int kc0, int s) {
        __half* Kf = KV + s * 2 * KV_K;
        __half* Vf = Kf + KV_K;
        #pragma unroll
        for (int i = 0; i < 2; i++) {
            int t = tid + i * 256;
            int r = t >> 3, ch = t & 7;
            size_t gk = (size_t)(b * KC + kc0 + r) * (2 * DD) + h * HD + ch * 8;
            cpa16(Kf + r * APITCH + ch * 8, g_kv_f + gk);
            cpa16(Vf + r * APITCH + ch * 8, g_kv_f + gk + DD);
        }
        asm volatile("cp.async.commit_group;\n");
    };

    // Q (fp16 split) folded into group 0
    #pragma unroll
    for (int i = 0; i < 4; i++) {
        int t = tid + i * 256;
        int r = t >> 3, ch = t & 7;
        size_t g = (size_t)(b * NN + n0 + r) * DD + h * HD + ch * 8;
        cpa16(Qh + r * APITCH + ch * 8, g_q_h + g);
        cpa16(Ql + r * APITCH + ch * 8, g_q_l + g);
    }
    loadKV(0, 0);
    loadKV(AKT, 1);

    uint32_t qh[4][4], ql[4][4];     // Q fragments, loaded once
    float oacc[8][4];
    #pragma unroll
    for (int nt = 0; nt < 8; nt++)
        #pragma unroll
        for (int e = 0; e < 4; e++) oacc[nt][e] = 0.f;
    float d0 = 0.f, d1 = 0.f;

    const int NIT = KC / AKT;   // 32
    for (int it = 0; it < NIT; it++) {
        if (it + 1 < NIT) asm volatile("cp.async.wait_group 1;\n");
        else              asm volatile("cp.async.wait_group 0;\n");
        __syncthreads();                 // stage it ready; stage it-1 drained

        if (it == 0) {
            #pragma unroll
            for (int d16 = 0; d16 < 4; d16++) {
                int r = wid * 16 + (lane & 7) + ((lane >> 3) & 1) * 8;
                int c = d16 * 16 + (lane >> 4) * 8;
                ldsm4(smem_u32(Qh + r * APITCH + c), qh[d16][0], qh[d16][1], qh[d16][2], qh[d16][3]);
                ldsm4(smem_u32(Ql + r * APITCH + c), ql[d16][0], ql[d16][1], ql[d16][2], ql[d16][3]);
            }
        }
        if (it + 2 < NIT) loadKV((it + 2) * AKT, (it + 2) % 3);

        __half* Kf = KV + (it % 3) * 2 * KV_K;
        __half* Vf = Kf + KV_K;

        // ---- S = Q @ K^T  (2 fp16 terms: Qh*K + Ql*K) ----
        float sacc[8][4];
        #pragma unroll
        for (int nt = 0; nt < 8; nt++)
            #pragma unroll
            for (int e = 0; e < 4; e++) sacc[nt][e] = 0.f;

        #pragma unroll
        for (int d16 = 0; d16 < 4; d16++) {
            const int dd0 = d16 * 16;
            uint32_t bh[8][2];
            #pragma unroll
            for (int np = 0; np < 4; np++) {
                int r = np * 16 + (lane & 7) + ((lane >> 4)) * 8;
                int c = dd0 + ((lane >> 3) & 1) * 8;
                uint32_t r0, r1, r2, r3;
                ldsm4(smem_u32(Kf + r * APITCH + c), r0, r1, r2, r3);
                bh[2*np][0]=r0; bh[2*np][1]=r1; bh[2*np+1][0]=r2; bh[2*np+1][1]=r3;
            }
            #pragma unroll
            for (int nt = 0; nt < 8; nt++) {
                mma_f16(sacc[nt], qh[d16], bh[nt]);
                mma_f16(sacc[nt], ql[d16], bh[nt]);
            }
        }

        // ---- P = exp(clip(S)) + partial row sums ----
        #pragma unroll
        for (int nt = 0; nt < 8; nt++) {
            #pragma unroll
            for (int e = 0; e < 4; e++)
                sacc[nt][e] = __expf(fminf(fmaxf(sacc[nt][e], -10.f), 10.f));
            d0 += sacc[nt][0] + sacc[nt][1];
            d1 += sacc[nt][2] + sacc[nt][3];
        }

        // ---- O += P @ V  (2 fp16 terms: Ph*V + Pl*V) ----
        #pragma unroll
        for (int c16 = 0; c16 < 4; c16++) {
            const int kk = c16 * 16;
            uint32_t ah[4], al[4];
            {
                const float* t0 = sacc[2*c16];
                const float* t1 = sacc[2*c16 + 1];
                packsplit_h(t0[0], t0[1], ah[0], al[0]);
                packsplit_h(t0[2], t0[3], ah[1], al[1]);
                packsplit_h(t1[0], t1[1], ah[2], al[2]);
                packsplit_h(t1[2], t1[3], ah[3], al[3]);
            }
            uint32_t bh[8][2];
            #pragma unroll
            for (int np = 0; np < 4; np++) {
                int rv = kk + (lane & 7) + ((lane >> 3) & 1) * 8;
                int cv = np * 16 + (lane >> 4) * 8;
                uint32_t r0, r1, r2, r3;
                ldsm4t(smem_u32(Vf + rv * APITCH + cv), r0, r1, r2, r3);
                bh[2*np][0]=r0; bh[2*np][1]=r1; bh[2*np+1][0]=r2; bh[2*np+1][1]=r3;
            }
            #pragma unroll
            for (int nt = 0; nt < 8; nt++) {
                mma_f16(oacc[nt], ah, bh[nt]);
                mma_f16(oacc[nt], al, bh[nt]);
            }
        }
    }

    // reduce row sums across the quad
    d0 += __shfl_xor_sync(0xffffffffu, d0, 1);
    d0 += __shfl_xor_sync(0xffffffffu, d0, 2);
    d1 += __shfl_xor_sync(0xffffffffu, d1, 1);
    d1 += __shfl_xor_sync(0xffffffffu, d1, 2);
    const float inv0 = 1.0f / d0;
    const float inv1 = 1.0f / d1;

    // normalize + write bf16-split output for the proj GEMM
    const int r0 = wid * 16 + (lane >> 2);
    #pragma unroll
    for (int nt = 0; nt < 8; nt++) {
        int c = nt * 8 + 2 * (lane & 3);
        size_t i0 = (size_t)(b * NN + n0 + r0) * DD + h * HD + c;
        size_t i1 = (size_t)(b * NN + n0 + r0 + 8) * DD + h * HD + c;
        uint32_t hh, ll;
        packsplit(oacc[nt][0] * inv0, oacc[nt][1] * inv0, hh, ll);
        *reinterpret_cast<uint32_t*>(g_ao_hi + i0) = hh;
        *reinterpret_cast<uint32_t*>(g_ao_lo + i0) = ll;
        packsplit(oacc[nt][2] * inv1, oacc[nt][3] * inv1, hh, ll);
        *reinterpret_cast<uint32_t*>(g_ao_hi + i1) = hh;
        *reinterpret_cast<uint32_t*>(g_ao_lo + i1) = ll;
    }
}

// ---------------------------------------------------------------------------
__global__ void finalize_mean(float* out, int out_size)
{
    const int base = BB * NN * DD;
    for (int i = base + threadIdx.x; i < out_size; i += blockDim.x)
        out[i] = 1.0f / (float)KC;
}

// ---------------------------------------------------------------------------
extern "C" void kernel_launch(void* const* d_in, const int* in_sizes, int n_in,
                              void* d_out, int out_size)
{
    const float* x      = (const float*)d_in[0];
    const float* ctx    = (const float*)d_in[1];
    const float* q_w    = (const float*)d_in[2];
    const float* q_b    = (const float*)d_in[3];
    const float* kv_w   = (const float*)d_in[4];
    const float* kv_b   = (const float*)d_in[5];
    const float* proj_w = (const float*)d_in[6];
    const float* proj_b = (const float*)d_in[7];
    float* out = (float*)d_out;

    __nv_bfloat16 *xh,*xl,*qwh,*qwl,*kvwh,*kvwl,*pwh,*pwl;
    cudaGetSymbolAddress((void**)&xh,  g_x_hi);  cudaGetSymbolAddress((void**)&xl,  g_x_lo);
    cudaGetSymbolAddress((void**)&qwh, g_qw_hi); cudaGetSymbolAddress((void**)&qwl, g_qw_lo);
    cudaGetSymbolAddress((void**)&kvwh,g_kvw_hi);cudaGetSymbolAddress((void**)&kvwl,g_kvw_lo);
    cudaGetSymbolAddress((void**)&pwh, g_pw_hi); cudaGetSymbolAddress((void**)&pwl, g_pw_lo);

    cudaFuncSetAttribute(mmgemm_qkv,  cudaFuncAttributeMaxDynamicSharedMemorySize, GEMM_SMEM);
    cudaFuncSetAttribute(mmgemm_proj, cudaFuncAttributeMaxDynamicSharedMemorySize, GEMM_SMEM);
    cudaFuncSetAttribute(attn_mma,    cudaFuncAttributeMaxDynamicSharedMemorySize, ATTN_SMEM);

    split_kernel<<<(BB*NN*DD/4 + 255)/256, 256>>>(x, xh, xl, BB*NN*DD);
    split_kernel<<<(DD*DD/4 + 255)/256, 256>>>(q_w, qwh, qwl, DD*DD);
    split_kernel<<<(DD*2*DD/4 + 255)/256, 256>>>(kv_w, kvwh, kvwl, DD*2*DD);
    split_kernel<<<(DD*DD/4 + 255)/256, 256>>>(proj_w, pwh, pwl, DD*DD);

    rmsnorm_split<<<BB*KC, 256>>>(ctx);

    // q (fp16 split, pre-scaled) + kv (fp16) merged
    mmgemm_qkv<<<dim3(24, BB*NN/GBM), 256, GEMM_SMEM>>>(q_b, kv_b);

    // attention (fp16 2-term)
    attn_mma<<<dim3(BB*HH, NN/ANT), 256, ATTN_SMEM>>>();

    // out = attn @ proj_w + proj_b (bf16 3-term, fp32 out)
    mmgemm_proj<<<dim3(DD/GBN, BB*NN/GBM), 256, GEMM_SMEM>>>(proj_b, out);

    if (out_size > BB * NN * DD)
        finalize_mean<<<1, 32>>>(out, out_size);
}

// round 12
// speedup vs baseline: 1.8971x; 1.2026x over previous
#include <cuda_runtime.h>
#include <cuda_bf16.h>
#include <cuda_fp16.h>
#include <cstdint>

#define BB 4
#define NN 2048
#define KC 2048
#define DD 1024
#define HH 16
#define HD 64
#define RMS_EPS 1e-6f

// ---------------------------------------------------------------------------
// Scratch (fp16 everywhere: A-sides split hi/lo, W-sides single)
// ---------------------------------------------------------------------------
__device__ __half g_x_h[BB*NN*DD],  g_x_l[BB*NN*DD];
__device__ __half g_cn_h[BB*KC*DD], g_cn_l[BB*KC*DD];
__device__ __half g_qw_f[DD*DD];
__device__ __half g_kvw_f[DD*2*DD];
__device__ __half g_pw_f[DD*DD];
__device__ __half g_q_h[BB*NN*DD],  g_q_l[BB*NN*DD];    // pre-scaled 0.125
__device__ __half g_kv_f[BB*KC*2*DD];
__device__ __half g_ao_h[BB*NN*DD], g_ao_l[BB*NN*DD];

// ---------------------------------------------------------------------------
// PTX helpers
// ---------------------------------------------------------------------------
__device__ __forceinline__ uint32_t smem_u32(const void* p) {
    return (uint32_t)__cvta_generic_to_shared(p);
}
__device__ __forceinline__ void ldsm4(uint32_t a, uint32_t& r0, uint32_t& r1,
                                      uint32_t& r2, uint32_t& r3) {
    asm volatile("ldmatrix.sync.aligned.m8n8.x4.shared.b16 {%0,%1,%2,%3}, [%4];"
                 : "=r"(r0), "=r"(r1), "=r"(r2), "=r"(r3) : "r"(a));
}
__device__ __forceinline__ void ldsm4t(uint32_t a, uint32_t& r0, uint32_t& r1,
                                       uint32_t& r2, uint32_t& r3) {
    asm volatile("ldmatrix.sync.aligned.m8n8.x4.trans.shared.b16 {%0,%1,%2,%3}, [%4];"
                 : "=r"(r0), "=r"(r1), "=r"(r2), "=r"(r3) : "r"(a));
}
__device__ __forceinline__ void mma_f16(float* c, const uint32_t* a, const uint32_t* b) {
    asm volatile(
        "mma.sync.aligned.m16n8k16.row.col.f32.f16.f16.f32 "
        "{%0,%1,%2,%3},{%4,%5,%6,%7},{%8,%9},{%0,%1,%2,%3};\n"
        : "+f"(c[0]), "+f"(c[1]), "+f"(c[2]), "+f"(c[3])
        : "r"(a[0]), "r"(a[1]), "r"(a[2]), "r"(a[3]), "r"(b[0]), "r"(b[1]));
}
__device__ __forceinline__ void cpa16(void* dst, const void* src) {
    uint32_t d = smem_u32(dst);
    asm volatile("cp.async.cg.shared.global [%0], [%1], 16;\n" :: "r"(d), "l"(src));
}
__device__ __forceinline__ uint32_t packh(float x, float y) {
    __half2 t = __floats2half2_rn(x, y);
    return *reinterpret_cast<uint32_t*>(&t);
}
__device__ __forceinline__ void packsplit_h(float x, float y, uint32_t& hi, uint32_t& lo) {
    __half hx = __float2half_rn(x), hy = __float2half_rn(y);
    __half2 hp = __halves2half2(hx, hy);
    hi = *reinterpret_cast<uint32_t*>(&hp);
    lo = packh(x - __half2float(hx), y - __half2float(hy));
}

// ---------------------------------------------------------------------------
// fp32 -> fp16 hi/lo split
// ---------------------------------------------------------------------------
__global__ __launch_bounds__(256) void split16_kernel(const float* __restrict__ src,
                                                      __half* __restrict__ hi,
                                                      __half* __restrict__ lo, int n)
{
    int i = (blockIdx.x * 256 + threadIdx.x) * 4;
    if (i >= n) return;
    float4 v = *reinterpret_cast<const float4*>(src + i);
    uint32_t h0, l0, h1, l1;
    packsplit_h(v.x, v.y, h0, l0);
    packsplit_h(v.z, v.w, h1, l1);
    *reinterpret_cast<uint2*>(hi + i) = make_uint2(h0, h1);
    *reinterpret_cast<uint2*>(lo + i) = make_uint2(l0, l1);
}

// fp32 -> fp16 single
__global__ __launch_bounds__(256) void conv16_kernel(const float* __restrict__ src,
                                                     __half* __restrict__ dst, int n)
{
    int i = (blockIdx.x * 256 + threadIdx.x) * 4;
    if (i >= n) return;
    float4 v = *reinterpret_cast<const float4*>(src + i);
    *reinterpret_cast<uint2*>(dst + i) = make_uint2(packh(v.x, v.y), packh(v.z, v.w));
}

// ---------------------------------------------------------------------------
// RMSNorm -> fp16 hi/lo
// ---------------------------------------------------------------------------
__global__ __launch_bounds__(256) void rmsnorm_split(const float* __restrict__ ctx)
{
    const int row = blockIdx.x;
    float4 v = reinterpret_cast<const float4*>(ctx + (size_t)row * DD)[threadIdx.x];
    float s = v.x*v.x + v.y*v.y + v.z*v.z + v.w*v.w;
    #pragma unroll
    for (int o = 16; o > 0; o >>= 1) s += __shfl_xor_sync(0xffffffffu, s, o);
    __shared__ float ws[8];
    if ((threadIdx.x & 31) == 0) ws[threadIdx.x >> 5] = s;
    __syncthreads();
    float tot = 0.f;
    #pragma unroll
    for (int i = 0; i < 8; i++) tot += ws[i];
    const float r = rsqrtf(tot * (1.0f / (float)DD) + RMS_EPS);
    const size_t base = (size_t)row * DD + threadIdx.x * 4;
    uint32_t h0, l0, h1, l1;
    packsplit_h(v.x * r, v.y * r, h0, l0);
    packsplit_h(v.z * r, v.w * r, h1, l1);
    *reinterpret_cast<uint2*>(g_cn_h + base) = make_uint2(h0, h1);
    *reinterpret_cast<uint2*>(g_cn_l + base) = make_uint2(l0, l1);
}

// ---------------------------------------------------------------------------
// fp16 2-term GEMM body: C = (Ah+Al)@Wf + bias.  128x128x32 tile, 256 thr,
// 3-stage cp.async pipeline, 1 sync/iter, 2 CTAs/SM.
// MODE: 0 = fp32 out, 2 = fp16 split out, 3 = fp16 single out
// ---------------------------------------------------------------------------
#define GBM 128
#define GBN 128
#define GBK 32
#define APAD 40
#define WPAD 136
#define A_EL (GBM*APAD)                       // 5120 halves
#define W_EL (GBK*WPAD)                       // 4352 halves
#define STG_EL (2*A_EL + W_EL)                // 14592 halves = 29184 B
#define GEMM_SMEM (3*STG_EL*2)                // 87552 B

template<int MODE>
__device__ __forceinline__ void gemm_body(
    __half* sm,
    const __half* __restrict__ Ah_g, const __half* __restrict__ Al_g,
    const __half* __restrict__ Wf_g,
    const float* __restrict__ bias, float scale,
    float* __restrict__ Cf, __half* __restrict__ H1, __half* __restrict__ H2,
    int rowBase, int colBase, int N, int K)
{
    const int tid = threadIdx.x;
    const int wid = tid >> 5, lane = tid & 31;
    const int wm = wid & 3;
    const int wn = wid >> 2;

    auto loadStage = [&](int kc, int s) {
        const int k0 = kc * GBK;
        __half* Ah = sm + s * STG_EL;
        __half* Al = Ah + A_EL;
        __half* Wf = Al + A_EL;
        #pragma unroll
        for (int i = 0; i < 2; i++) {
            int t = tid + i * 256;
            int r = t >> 2, ch = t & 3;
            size_t ga = (size_t)(rowBase + r) * K + k0 + ch * 8;
            cpa16(Ah + r * APAD + ch * 8, Ah_g + ga);
            cpa16(Al + r * APAD + ch * 8, Al_g + ga);
            int rw = t >> 4, cw = t & 15;
            size_t gw = (size_t)(k0 + rw) * N + colBase + cw * 8;
            cpa16(Wf + rw * WPAD + cw * 8, Wf_g + gw);
        }
        asm volatile("cp.async.commit_group;\n");
    };

    float acc[2][8][4];
    #pragma unroll
    for (int mt = 0; mt < 2; mt++)
        #pragma unroll
        for (int nt = 0; nt < 8; nt++)
            #pragma unroll
            for (int e = 0; e < 4; e++) acc[mt][nt][e] = 0.f;

    const int NK = K / GBK;
    loadStage(0, 0);
    loadStage(1, 1);
    for (int kc = 0; kc < NK; kc++) {
        if (kc + 1 < NK) asm volatile("cp.async.wait_group 1;\n");
        else             asm volatile("cp.async.wait_group 0;\n");
        __syncthreads();
        if (kc + 2 < NK) loadStage(kc + 2, (kc + 2) % 3);

        __half* Ah = sm + (kc % 3) * STG_EL;
        __half* Al = Ah + A_EL;
        __half* Wf = Al + A_EL;

        #pragma unroll
        for (int k16 = 0; k16 < 2; k16++) {
            const int kk = k16 * 16;
            uint32_t ah[2][4], al[2][4];
            #pragma unroll
            for (int mt = 0; mt < 2; mt++) {
                int r = wm * 32 + mt * 16 + (lane & 7) + ((lane >> 3) & 1) * 8;
                int c = kk + (lane >> 4) * 8;
                ldsm4(smem_u32(Ah + r * APAD + c), ah[mt][0], ah[mt][1], ah[mt][2], ah[mt][3]);
                ldsm4(smem_u32(Al + r * APAD + c), al[mt][0], al[mt][1], al[mt][2], al[mt][3]);
            }
            uint32_t bw[8][2];
            #pragma unroll
            for (int np = 0; np < 4; np++) {
                int r = kk + (lane & 7) + ((lane >> 3) & 1) * 8;
                int c = wn * 64 + np * 16 + (lane >> 4) * 8;
                uint32_t r0, r1, r2, r3;
                ldsm4t(smem_u32(Wf + r * WPAD + c), r0, r1, r2, r3);
                bw[2*np][0]=r0; bw[2*np][1]=r1; bw[2*np+1][0]=r2; bw[2*np+1][1]=r3;
            }
            #pragma unroll
            for (int mt = 0; mt < 2; mt++)
                #pragma unroll
                for (int nt = 0; nt < 8; nt++) {
                    mma_f16(acc[mt][nt], ah[mt], bw[nt]);
                    mma_f16(acc[mt][nt], al[mt], bw[nt]);
                }
        }
    }

    #pragma unroll
    for (int mt = 0; mt < 2; mt++)
        #pragma unroll
        for (int nt = 0; nt < 8; nt++) {
            int row = rowBase + wm * 32 + mt * 16 + (lane >> 2);
            int col = colBase + wn * 64 + nt * 8 + 2 * (lane & 3);
            float b0 = bias[col], b1 = bias[col + 1];
            float v00 = (acc[mt][nt][0] + b0) * scale;
            float v01 = (acc[mt][nt][1] + b1) * scale;
            float v10 = (acc[mt][nt][2] + b0) * scale;
            float v11 = (acc[mt][nt][3] + b1) * scale;
            size_t i0 = (size_t)row * N + col;
            size_t i1 = (size_t)(row + 8) * N + col;
            if (MODE == 0) {
                *reinterpret_cast<float2*>(Cf + i0) = make_float2(v00, v01);
                *reinterpret_cast<float2*>(Cf + i1) = make_float2(v10, v11);
            } else if (MODE == 2) {
                uint32_t h, l;
                packsplit_h(v00, v01, h, l);
                *reinterpret_cast<uint32_t*>(H1 + i0) = h;
                *reinterpret_cast<uint32_t*>(H2 + i0) = l;
                packsplit_h(v10, v11, h, l);
                *reinterpret_cast<uint32_t*>(H1 + i1) = h;
                *reinterpret_cast<uint32_t*>(H2 + i1) = l;
            } else {
                *reinterpret_cast<uint32_t*>(H1 + i0) = packh(v00, v01);
                *reinterpret_cast<uint32_t*>(H1 + i1) = packh(v10, v11);
            }
        }
}

// Merged q + kv projection: blocks 0-7 -> q (fp16 split out), 8-23 -> kv (fp16)
__global__ __launch_bounds__(256, 2) void mmgemm_qkv(
    const float* __restrict__ q_b, const float* __restrict__ kv_b)
{
    extern __shared__ __half smg[];
    if (blockIdx.x < 8) {
        gemm_body<2>(smg, g_x_h, g_x_l, g_qw_f, q_b, 0.125f,
                     nullptr, g_q_h, g_q_l,
                     blockIdx.y * GBM, blockIdx.x * GBN, DD, DD);
    } else {
        gemm_body<3>(smg, g_cn_h, g_cn_l, g_kvw_f, kv_b, 1.0f,
                     nullptr, g_kv_f, nullptr,
                     blockIdx.y * GBM, (blockIdx.x - 8) * GBN, 2 * DD, DD);
    }
}

__global__ __launch_bounds__(256, 2) void mmgemm_proj(
    const float* __restrict__ proj_b, float* __restrict__ out)
{
    extern __shared__ __half smg[];
    gemm_body<0>(smg, g_ao_h, g_ao_l, g_pw_f, proj_b, 1.0f,
                 out, nullptr, nullptr,
                 blockIdx.y * GBM, blockIdx.x * GBN, DD, DD);
}

// ---------------------------------------------------------------------------
// Attention (R9-validated): fp16 2-term QK and PV, Q fragments in registers,
// 3-stage single-sync KV pipeline, 2 CTAs/SM. Epilogue now fp16-split.
// ---------------------------------------------------------------------------
#define ANT 128
#define AKT 64
#define APITCH 72
#define Q_EL (ANT*APITCH)            // 9216 halves
#define KV_K (AKT*APITCH)            // 4608 halves per array
#define ATTN_SMEM ((2*Q_EL + 6*KV_K) * 2)

__global__ __launch_bounds__(256, 2) void attn_mma()
{
    extern __shared__ __half smh[];
    __half* Qh = smh;
    __half* Ql = Qh + Q_EL;
    __half* KV = Ql + Q_EL;          // stage s: K at KV + s*2*KV_K, V at +KV_K

    const int tid = threadIdx.x, wid = tid >> 5, lane = tid & 31;
    const int b = blockIdx.x >> 4, h = blockIdx.x & 15;
    const int n0 = blockIdx.y * ANT;

    auto loadKV = [&](int kc0, int s) {
        __half* Kf = KV + s * 2 * KV_K;
        __half* Vf = Kf + KV_K;
        #pragma unroll
        for (int i = 0; i < 2; i++) {
            int t = tid + i * 256;
            int r = t >> 3, ch = t & 7;
            size_t gk = (size_t)(b * KC + kc0 + r) * (2 * DD) + h * HD + ch * 8;
            cpa16(Kf + r * APITCH + ch * 8, g_kv_f + gk);
            cpa16(Vf + r * APITCH + ch * 8, g_kv_f + gk + DD);
        }
        asm volatile("cp.async.commit_group;\n");
    };

    // Q (fp16 split) folded into group 0
    #pragma unroll
    for (int i = 0; i < 4; i++) {
        int t = tid + i * 256;
        int r = t >> 3, ch = t & 7;
        size_t g = (size_t)(b * NN + n0 + r) * DD + h * HD + ch * 8;
        cpa16(Qh + r * APITCH + ch * 8, g_q_h + g);
        cpa16(Ql + r * APITCH + ch * 8, g_q_l + g);
    }
    loadKV(0, 0);
    loadKV(AKT, 1);

    uint32_t qh[4][4], ql[4][4];
    float oacc[8][4];
    #pragma unroll
    for (int nt = 0; nt < 8; nt++)
        #pragma unroll
        for (int e = 0; e < 4; e++) oacc[nt][e] = 0.f;
    float d0 = 0.f, d1 = 0.f;

    const int NIT = KC / AKT;   // 32
    for (int it = 0; it < NIT; it++) {
        if (it + 1 < NIT) asm volatile("cp.async.wait_group 1;\n");
        else              asm volatile("cp.async.wait_group 0;\n");
        __syncthreads();

        if (it == 0) {
            #pragma unroll
            for (int d16 = 0; d16 < 4; d16++) {
                int r = wid * 16 + (lane & 7) + ((lane >> 3) & 1) * 8;
                int c = d16 * 16 + (lane >> 4) * 8;
                ldsm4(smem_u32(Qh + r * APITCH + c), qh[d16][0], qh[d16][1], qh[d16][2], qh[d16][3]);
                ldsm4(smem_u32(Ql + r * APITCH + c), ql[d16][0], ql[d16][1], ql[d16][2], ql[d16][3]);
            }
        }
        if (it + 2 < NIT) loadKV((it + 2) * AKT, (it + 2) % 3);

        __half* Kf = KV + (it % 3) * 2 * KV_K;
        __half* Vf = Kf + KV_K;

        // ---- S = Q @ K^T ----
        float sacc[8][4];
        #pragma unroll
        for (int nt = 0; nt < 8; nt++)
            #pragma unroll
            for (int e = 0; e < 4; e++) sacc[nt][e] = 0.f;

        #pragma unroll
        for (int d16 = 0; d16 < 4; d16++) {
            const int dd0 = d16 * 16;
            uint32_t bh[8][2];
            #pragma unroll
            for (int np = 0; np < 4; np++) {
                int r = np * 16 + (lane & 7) + ((lane >> 4)) * 8;
                int c = dd0 + ((lane >> 3) & 1) * 8;
                uint32_t r0, r1, r2, r3;
                ldsm4(smem_u32(Kf + r * APITCH + c), r0, r1, r2, r3);
                bh[2*np][0]=r0; bh[2*np][1]=r1; bh[2*np+1][0]=r2; bh[2*np+1][1]=r3;
            }
            #pragma unroll
            for (int nt = 0; nt < 8; nt++) {
                mma_f16(sacc[nt], qh[d16], bh[nt]);
                mma_f16(sacc[nt], ql[d16], bh[nt]);
            }
        }

        // ---- P = exp(clip(S)) + partial row sums ----
        #pragma unroll
        for (int nt = 0; nt < 8; nt++) {
            #pragma unroll
            for (int e = 0; e < 4; e++)
                sacc[nt][e] = __expf(fminf(fmaxf(sacc[nt][e], -10.f), 10.f));
            d0 += sacc[nt][0] + sacc[nt][1];
            d1 += sacc[nt][2] + sacc[nt][3];
        }

        // ---- O += P @ V (register-direct P, 2 fp16 terms) ----
        #pragma unroll
        for (int c16 = 0; c16 < 4; c16++) {
            const int kk = c16 * 16;
            uint32_t ah[4], al[4];
            {
                const float* t0 = sacc[2*c16];
                const float* t1 = sacc[2*c16 + 1];
                packsplit_h(t0[0], t0[1], ah[0], al[0]);
                packsplit_h(t0[2], t0[3], ah[1], al[1]);
                packsplit_h(t1[0], t1[1], ah[2], al[2]);
                packsplit_h(t1[2], t1[3], ah[3], al[3]);
            }
            uint32_t bh[8][2];
            #pragma unroll
            for (int np = 0; np < 4; np++) {
                int rv = kk + (lane & 7) + ((lane >> 3) & 1) * 8;
                int cv = np * 16 + (lane >> 4) * 8;
                uint32_t r0, r1, r2, r3;
                ldsm4t(smem_u32(Vf + rv * APITCH + cv), r0, r1, r2, r3);
                bh[2*np][0]=r0; bh[2*np][1]=r1; bh[2*np+1][0]=r2; bh[2*np+1][1]=r3;
            }
            #pragma unroll
            for (int nt = 0; nt < 8; nt++) {
                mma_f16(oacc[nt], ah, bh[nt]);
                mma_f16(oacc[nt], al, bh[nt]);
            }
        }
    }

    // reduce row sums across the quad
    d0 += __shfl_xor_sync(0xffffffffu, d0, 1);
    d0 += __shfl_xor_sync(0xffffffffu, d0, 2);
    d1 += __shfl_xor_sync(0xffffffffu, d1, 1);
    d1 += __shfl_xor_sync(0xffffffffu, d1, 2);
    const float inv0 = 1.0f / d0;
    const float inv1 = 1.0f / d1;

    // normalize + write fp16-split output for the proj GEMM
    const int r0 = wid * 16 + (lane >> 2);
    #pragma unroll
    for (int nt = 0; nt < 8; nt++) {
        int c = nt * 8 + 2 * (lane & 3);
        size_t i0 = (size_t)(b * NN + n0 + r0) * DD + h * HD + c;
        size_t i1 = (size_t)(b * NN + n0 + r0 + 8) * DD + h * HD + c;
        uint32_t hh, ll;
        packsplit_h(oacc[nt][0] * inv0, oacc[nt][1] * inv0, hh, ll);
        *reinterpret_cast<uint32_t*>(g_ao_h + i0) = hh;
        *reinterpret_cast<uint32_t*>(g_ao_l + i0) = ll;
        packsplit_h(oacc[nt][2] * inv1, oacc[nt][3] * inv1, hh, ll);
        *reinterpret_cast<uint32_t*>(g_ao_h + i1) = hh;
        *reinterpret_cast<uint32_t*>(g_ao_l + i1) = ll;
    }
}

// ---------------------------------------------------------------------------
__global__ void finalize_mean(float* out, int out_size)
{
    const int base = BB * NN * DD;
    for (int i = base + threadIdx.x; i < out_size; i += blockDim.x)
        out[i] = 1.0f / (float)KC;
}

// ---------------------------------------------------------------------------
extern "C" void kernel_launch(void* const* d_in, const int* in_sizes, int n_in,
                              void* d_out, int out_size)
{
    const float* x      = (const float*)d_in[0];
    const float* ctx    = (const float*)d_in[1];
    const float* q_w    = (const float*)d_in[2];
    const float* q_b    = (const float*)d_in[3];
    const float* kv_w   = (const float*)d_in[4];
    const float* kv_b   = (const float*)d_in[5];
    const float* proj_w = (const float*)d_in[6];
    const float* proj_b = (const float*)d_in[7];
    float* out = (float*)d_out;

    __half *xh, *xl, *qwf, *kvwf, *pwf;
    cudaGetSymbolAddress((void**)&xh,   g_x_h);
    cudaGetSymbolAddress((void**)&xl,   g_x_l);
    cudaGetSymbolAddress((void**)&qwf,  g_qw_f);
    cudaGetSymbolAddress((void**)&kvwf, g_kvw_f);
    cudaGetSymbolAddress((void**)&pwf,  g_pw_f);

    cudaFuncSetAttribute(mmgemm_qkv,  cudaFuncAttributeMaxDynamicSharedMemorySize, GEMM_SMEM);
    cudaFuncSetAttribute(mmgemm_proj, cudaFuncAttributeMaxDynamicSharedMemorySize, GEMM_SMEM);
    cudaFuncSetAttribute(attn_mma,    cudaFuncAttributeMaxDynamicSharedMemorySize, ATTN_SMEM);

    split16_kernel<<<(BB*NN*DD/4 + 255)/256, 256>>>(x, xh, xl, BB*NN*DD);
    conv16_kernel<<<(DD*DD/4 + 255)/256, 256>>>(q_w, qwf, DD*DD);
    conv16_kernel<<<(DD*2*DD/4 + 255)/256, 256>>>(kv_w, kvwf, DD*2*DD);
    conv16_kernel<<<(DD*DD/4 + 255)/256, 256>>>(proj_w, pwf, DD*DD);

    rmsnorm_split<<<BB*KC, 256>>>(ctx);

    // q (fp16 split, pre-scaled) + kv (fp16) merged
    mmgemm_qkv<<<dim3(24, BB*NN/GBM), 256, GEMM_SMEM>>>(q_b, kv_b);

    // attention (fp16 2-term)
    attn_mma<<<dim3(BB*HH, NN/ANT), 256, ATTN_SMEM>>>();

    // out = attn @ proj_w + proj_b (fp16 2-term, fp32 out)
    mmgemm_proj<<<dim3(DD/GBN, BB*NN/GBM), 256, GEMM_SMEM>>>(proj_b, out);

    if (out_size > BB * NN * DD)
        finalize_mean<<<1, 32>>>(out, out_size);
}

// round 13
// speedup vs baseline: 2.3142x; 1.2198x over previous
#include <cuda_runtime.h>
#include <cuda_bf16.h>
#include <cuda_fp16.h>
#include <cstdint>

#define BB 4
#define NN 2048
#define KC 2048
#define DD 1024
#define HH 16
#define HD 64
#define RMS_EPS 1e-6f

// ---------------------------------------------------------------------------
// Scratch (fp16: GEMM A-sides split hi/lo, weights + attention operands single)
// ---------------------------------------------------------------------------
__device__ __half g_x_h[BB*NN*DD],  g_x_l[BB*NN*DD];
__device__ __half g_cn_h[BB*KC*DD], g_cn_l[BB*KC*DD];
__device__ __half g_qw_f[DD*DD];
__device__ __half g_kvw_f[DD*2*DD];
__device__ __half g_pw_f[DD*DD];
__device__ __half g_q_f[BB*NN*DD];                      // single fp16, pre-scaled 0.125
__device__ __half g_kv_f[BB*KC*2*DD];
__device__ __half g_ao_h[BB*NN*DD], g_ao_l[BB*NN*DD];

// ---------------------------------------------------------------------------
// PTX helpers
// ---------------------------------------------------------------------------
__device__ __forceinline__ uint32_t smem_u32(const void* p) {
    return (uint32_t)__cvta_generic_to_shared(p);
}
__device__ __forceinline__ void ldsm4(uint32_t a, uint32_t& r0, uint32_t& r1,
                                      uint32_t& r2, uint32_t& r3) {
    asm volatile("ldmatrix.sync.aligned.m8n8.x4.shared.b16 {%0,%1,%2,%3}, [%4];"
                 : "=r"(r0), "=r"(r1), "=r"(r2), "=r"(r3) : "r"(a));
}
__device__ __forceinline__ void ldsm4t(uint32_t a, uint32_t& r0, uint32_t& r1,
                                       uint32_t& r2, uint32_t& r3) {
    asm volatile("ldmatrix.sync.aligned.m8n8.x4.trans.shared.b16 {%0,%1,%2,%3}, [%4];"
                 : "=r"(r0), "=r"(r1), "=r"(r2), "=r"(r3) : "r"(a));
}
__device__ __forceinline__ void mma_f16(float* c, const uint32_t* a, const uint32_t* b) {
    asm volatile(
        "mma.sync.aligned.m16n8k16.row.col.f32.f16.f16.f32 "
        "{%0,%1,%2,%3},{%4,%5,%6,%7},{%8,%9},{%0,%1,%2,%3};\n"
        : "+f"(c[0]), "+f"(c[1]), "+f"(c[2]), "+f"(c[3])
        : "r"(a[0]), "r"(a[1]), "r"(a[2]), "r"(a[3]), "r"(b[0]), "r"(b[1]));
}
__device__ __forceinline__ void cpa16(void* dst, const void* src) {
    uint32_t d = smem_u32(dst);
    asm volatile("cp.async.cg.shared.global [%0], [%1], 16;\n" :: "r"(d), "l"(src));
}
__device__ __forceinline__ uint32_t packh(float x, float y) {
    __half2 t = __floats2half2_rn(x, y);
    return *reinterpret_cast<uint32_t*>(&t);
}
__device__ __forceinline__ void packsplit_h(float x, float y, uint32_t& hi, uint32_t& lo) {
    __half hx = __float2half_rn(x), hy = __float2half_rn(y);
    __half2 hp = __halves2half2(hx, hy);
    hi = *reinterpret_cast<uint32_t*>(&hp);
    lo = packh(x - __half2float(hx), y - __half2float(hy));
}

// ---------------------------------------------------------------------------
// fp32 -> fp16 hi/lo split
// ---------------------------------------------------------------------------
__global__ __launch_bounds__(256) void split16_kernel(const float* __restrict__ src,
                                                      __half* __restrict__ hi,
                                                      __half* __restrict__ lo, int n)
{
    int i = (blockIdx.x * 256 + threadIdx.x) * 4;
    if (i >= n) return;
    float4 v = *reinterpret_cast<const float4*>(src + i);
    uint32_t h0, l0, h1, l1;
    packsplit_h(v.x, v.y, h0, l0);
    packsplit_h(v.z, v.w, h1, l1);
    *reinterpret_cast<uint2*>(hi + i) = make_uint2(h0, h1);
    *reinterpret_cast<uint2*>(lo + i) = make_uint2(l0, l1);
}

// fp32 -> fp16 single
__global__ __launch_bounds__(256) void conv16_kernel(const float* __restrict__ src,
                                                     __half* __restrict__ dst, int n)
{
    int i = (blockIdx.x * 256 + threadIdx.x) * 4;
    if (i >= n) return;
    float4 v = *reinterpret_cast<const float4*>(src + i);
    *reinterpret_cast<uint2*>(dst + i) = make_uint2(packh(v.x, v.y), packh(v.z, v.w));
}

// ---------------------------------------------------------------------------
// RMSNorm -> fp16 hi/lo
// ---------------------------------------------------------------------------
__global__ __launch_bounds__(256) void rmsnorm_split(const float* __restrict__ ctx)
{
    const int row = blockIdx.x;
    float4 v = reinterpret_cast<const float4*>(ctx + (size_t)row * DD)[threadIdx.x];
    float s = v.x*v.x + v.y*v.y + v.z*v.z + v.w*v.w;
    #pragma unroll
    for (int o = 16; o > 0; o >>= 1) s += __shfl_xor_sync(0xffffffffu, s, o);
    __shared__ float ws[8];
    if ((threadIdx.x & 31) == 0) ws[threadIdx.x >> 5] = s;
    __syncthreads();
    float tot = 0.f;
    #pragma unroll
    for (int i = 0; i < 8; i++) tot += ws[i];
    const float r = rsqrtf(tot * (1.0f / (float)DD) + RMS_EPS);
    const size_t base = (size_t)row * DD + threadIdx.x * 4;
    uint32_t h0, l0, h1, l1;
    packsplit_h(v.x * r, v.y * r, h0, l0);
    packsplit_h(v.z * r, v.w * r, h1, l1);
    *reinterpret_cast<uint2*>(g_cn_h + base) = make_uint2(h0, h1);
    *reinterpret_cast<uint2*>(g_cn_l + base) = make_uint2(l0, l1);
}

// ---------------------------------------------------------------------------
// fp16 2-term GEMM body (R11-validated): C = (Ah+Al)@Wf + bias.
// 128x128x32 tile, 3-stage pipeline, 1 sync/iter, 2 CTAs/SM.
// MODE: 0 = fp32 out, 2 = fp16 split out, 3 = fp16 single out
// ---------------------------------------------------------------------------
#define GBM 128
#define GBN 128
#define GBK 32
#define APAD 40
#define WPAD 136
#define A_EL (GBM*APAD)
#define W_EL (GBK*WPAD)
#define STG_EL (2*A_EL + W_EL)
#define GEMM_SMEM (3*STG_EL*2)

template<int MODE>
__device__ __forceinline__ void gemm_body(
    __half* sm,
    const __half* __restrict__ Ah_g, const __half* __restrict__ Al_g,
    const __half* __restrict__ Wf_g,
    const float* __restrict__ bias, float scale,
    float* __restrict__ Cf, __half* __restrict__ H1, __half* __restrict__ H2,
    int rowBase, int colBase, int N, int K)
{
    const int tid = threadIdx.x;
    const int wid = tid >> 5, lane = tid & 31;
    const int wm = wid & 3;
    const int wn = wid >> 2;

    auto loadStage = [&](int kc, int s) {
        const int k0 = kc * GBK;
        __half* Ah = sm + s * STG_EL;
        __half* Al = Ah + A_EL;
        __half* Wf = Al + A_EL;
        #pragma unroll
        for (int i = 0; i < 2; i++) {
            int t = tid + i * 256;
            int r = t >> 2, ch = t & 3;
            size_t ga = (size_t)(rowBase + r) * K + k0 + ch * 8;
            cpa16(Ah + r * APAD + ch * 8, Ah_g + ga);
            cpa16(Al + r * APAD + ch * 8, Al_g + ga);
            int rw = t >> 4, cw = t & 15;
            size_t gw = (size_t)(k0 + rw) * N + colBase + cw * 8;
            cpa16(Wf + rw * WPAD + cw * 8, Wf_g + gw);
        }
        asm volatile("cp.async.commit_group;\n");
    };

    float acc[2][8][4];
    #pragma unroll
    for (int mt = 0; mt < 2; mt++)
        #pragma unroll
        for (int nt = 0; nt < 8; nt++)
            #pragma unroll
            for (int e = 0; e < 4; e++) acc[mt][nt][e] = 0.f;

    const int NK = K / GBK;
    loadStage(0, 0);
    loadStage(1, 1);
    for (int kc = 0; kc < NK; kc++) {
        if (kc + 1 < NK) asm volatile("cp.async.wait_group 1;\n");
        else             asm volatile("cp.async.wait_group 0;\n");
        __syncthreads();
        if (kc + 2 < NK) loadStage(kc + 2, (kc + 2) % 3);

        __half* Ah = sm + (kc % 3) * STG_EL;
        __half* Al = Ah + A_EL;
        __half* Wf = Al + A_EL;

        #pragma unroll
        for (int k16 = 0; k16 < 2; k16++) {
            const int kk = k16 * 16;
            uint32_t ah[2][4], al[2][4];
            #pragma unroll
            for (int mt = 0; mt < 2; mt++) {
                int r = wm * 32 + mt * 16 + (lane & 7) + ((lane >> 3) & 1) * 8;
                int c = kk + (lane >> 4) * 8;
                ldsm4(smem_u32(Ah + r * APAD + c), ah[mt][0], ah[mt][1], ah[mt][2], ah[mt][3]);
                ldsm4(smem_u32(Al + r * APAD + c), al[mt][0], al[mt][1], al[mt][2], al[mt][3]);
            }
            uint32_t bw[8][2];
            #pragma unroll
            for (int np = 0; np < 4; np++) {
                int r = kk + (lane & 7) + ((lane >> 3) & 1) * 8;
                int c = wn * 64 + np * 16 + (lane >> 4) * 8;
                uint32_t r0, r1, r2, r3;
                ldsm4t(smem_u32(Wf + r * WPAD + c), r0, r1, r2, r3);
                bw[2*np][0]=r0; bw[2*np][1]=r1; bw[2*np+1][0]=r2; bw[2*np+1][1]=r3;
            }
            #pragma unroll
            for (int mt = 0; mt < 2; mt++)
                #pragma unroll
                for (int nt = 0; nt < 8; nt++) {
                    mma_f16(acc[mt][nt], ah[mt], bw[nt]);
                    mma_f16(acc[mt][nt], al[mt], bw[nt]);
                }
        }
    }

    #pragma unroll
    for (int mt = 0; mt < 2; mt++)
        #pragma unroll
        for (int nt = 0; nt < 8; nt++) {
            int row = rowBase + wm * 32 + mt * 16 + (lane >> 2);
            int col = colBase + wn * 64 + nt * 8 + 2 * (lane & 3);
            float b0 = bias[col], b1 = bias[col + 1];
            float v00 = (acc[mt][nt][0] + b0) * scale;
            float v01 = (acc[mt][nt][1] + b1) * scale;
            float v10 = (acc[mt][nt][2] + b0) * scale;
            float v11 = (acc[mt][nt][3] + b1) * scale;
            size_t i0 = (size_t)row * N + col;
            size_t i1 = (size_t)(row + 8) * N + col;
            if (MODE == 0) {
                *reinterpret_cast<float2*>(Cf + i0) = make_float2(v00, v01);
                *reinterpret_cast<float2*>(Cf + i1) = make_float2(v10, v11);
            } else if (MODE == 2) {
                uint32_t h, l;
                packsplit_h(v00, v01, h, l);
                *reinterpret_cast<uint32_t*>(H1 + i0) = h;
                *reinterpret_cast<uint32_t*>(H2 + i0) = l;
                packsplit_h(v10, v11, h, l);
                *reinterpret_cast<uint32_t*>(H1 + i1) = h;
                *reinterpret_cast<uint32_t*>(H2 + i1) = l;
            } else {
                *reinterpret_cast<uint32_t*>(H1 + i0) = packh(v00, v01);
                *reinterpret_cast<uint32_t*>(H1 + i1) = packh(v10, v11);
            }
        }
}

// Merged q + kv projection: blocks 0-7 -> q (fp16 single), 8-23 -> kv (fp16 single)
__global__ __launch_bounds__(256, 2) void mmgemm_qkv(
    const float* __restrict__ q_b, const float* __restrict__ kv_b)
{
    extern __shared__ __half smg[];
    if (blockIdx.x < 8) {
        gemm_body<3>(smg, g_x_h, g_x_l, g_qw_f, q_b, 0.125f,
                     nullptr, g_q_f, nullptr,
                     blockIdx.y * GBM, blockIdx.x * GBN, DD, DD);
    } else {
        gemm_body<3>(smg, g_cn_h, g_cn_l, g_kvw_f, kv_b, 1.0f,
                     nullptr, g_kv_f, nullptr,
                     blockIdx.y * GBM, (blockIdx.x - 8) * GBN, 2 * DD, DD);
    }
}

__global__ __launch_bounds__(256, 2) void mmgemm_proj(
    const float* __restrict__ proj_b, float* __restrict__ out)
{
    extern __shared__ __half smg[];
    gemm_body<0>(smg, g_ao_h, g_ao_l, g_pw_f, proj_b, 1.0f,
                 out, nullptr, nullptr,
                 blockIdx.y * GBM, blockIdx.x * GBN, DD, DD);
}

// ---------------------------------------------------------------------------
// Attention v4: fully single-fp16 (1-term QK, 1-term PV), Q fragments in
// registers, 3-stage single-sync KV pipeline, 2 CTAs/SM.
// smem: Q (fp16 128x72) + 3 stages of (K,V) 64x72 = 73728 B
// ---------------------------------------------------------------------------
#define ANT 128
#define AKT 64
#define APITCH 72
#define Q_EL (ANT*APITCH)            // 9216 halves
#define KV_K (AKT*APITCH)            // 4608 halves per array
#define ATTN_SMEM ((Q_EL + 6*KV_K) * 2)

__global__ __launch_bounds__(256, 2) void attn_mma()
{
    extern __shared__ __half smh[];
    __half* Qf = smh;
    __half* KV = Qf + Q_EL;          // stage s: K at KV + s*2*KV_K, V at +KV_K

    const int tid = threadIdx.x, wid = tid >> 5, lane = tid & 31;
    const int b = blockIdx.x >> 4, h = blockIdx.x & 15;
    const int n0 = blockIdx.y * ANT;

    auto loadKV = [&](int kc0, int s) {
        __half* Kf = KV + s * 2 * KV_K;
        __half* Vf = Kf + KV_K;
        #pragma unroll
        for (int i = 0; i < 2; i++) {
            int t = tid + i * 256;
            int r = t >> 3, ch = t & 7;
            size_t gk = (size_t)(b * KC + kc0 + r) * (2 * DD) + h * HD + ch * 8;
            cpa16(Kf + r * APITCH + ch * 8, g_kv_f + gk);
            cpa16(Vf + r * APITCH + ch * 8, g_kv_f + gk + DD);
        }
        asm volatile("cp.async.commit_group;\n");
    };

    // Q (single fp16) folded into group 0
    #pragma unroll
    for (int i = 0; i < 2; i++) {
        int t = tid + i * 256;
        int r = t >> 2, ch = t & 3;
        size_t g = (size_t)(b * NN + n0 + r) * DD + h * HD + ch * 16;
        cpa16(Qf + r * APITCH + ch * 16, g_q_f + g);
        cpa16(Qf + r * APITCH + ch * 16 + 8, g_q_f + g + 8);
    }
    loadKV(0, 0);
    loadKV(AKT, 1);

    uint32_t qf[4][4];               // Q fragments, loaded once
    float oacc[8][4];
    #pragma unroll
    for (int nt = 0; nt < 8; nt++)
        #pragma unroll
        for (int e = 0; e < 4; e++) oacc[nt][e] = 0.f;
    float d0 = 0.f, d1 = 0.f;

    const int NIT = KC / AKT;   // 32
    for (int it = 0; it < NIT; it++) {
        if (it + 1 < NIT) asm volatile("cp.async.wait_group 1;\n");
        else              asm volatile("cp.async.wait_group 0;\n");
        __syncthreads();

        if (it == 0) {
            #pragma unroll
            for (int d16 = 0; d16 < 4; d16++) {
                int r = wid * 16 + (lane & 7) + ((lane >> 3) & 1) * 8;
                int c = d16 * 16 + (lane >> 4) * 8;
                ldsm4(smem_u32(Qf + r * APITCH + c), qf[d16][0], qf[d16][1], qf[d16][2], qf[d16][3]);
            }
        }
        if (it + 2 < NIT) loadKV((it + 2) * AKT, (it + 2) % 3);

        __half* Kf = KV + (it % 3) * 2 * KV_K;
        __half* Vf = Kf + KV_K;

        // ---- S = Q @ K^T  (1 fp16 term) ----
        float sacc[8][4];
        #pragma unroll
        for (int nt = 0; nt < 8; nt++)
            #pragma unroll
            for (int e = 0; e < 4; e++) sacc[nt][e] = 0.f;

        #pragma unroll
        for (int d16 = 0; d16 < 4; d16++) {
            const int dd0 = d16 * 16;
            uint32_t bh[8][2];
            #pragma unroll
            for (int np = 0; np < 4; np++) {
                int r = np * 16 + (lane & 7) + ((lane >> 4)) * 8;
                int c = dd0 + ((lane >> 3) & 1) * 8;
                uint32_t r0, r1, r2, r3;
                ldsm4(smem_u32(Kf + r * APITCH + c), r0, r1, r2, r3);
                bh[2*np][0]=r0; bh[2*np][1]=r1; bh[2*np+1][0]=r2; bh[2*np+1][1]=r3;
            }
            #pragma unroll
            for (int nt = 0; nt < 8; nt++)
                mma_f16(sacc[nt], qf[d16], bh[nt]);
        }

        // ---- P = exp(clip(S)) + partial row sums ----
        #pragma unroll
        for (int nt = 0; nt < 8; nt++) {
            #pragma unroll
            for (int e = 0; e < 4; e++)
                sacc[nt][e] = __expf(fminf(fmaxf(sacc[nt][e], -10.f), 10.f));
            d0 += sacc[nt][0] + sacc[nt][1];
            d1 += sacc[nt][2] + sacc[nt][3];
        }

        // ---- O += P @ V  (register-direct P, 1 fp16 term) ----
        #pragma unroll
        for (int c16 = 0; c16 < 4; c16++) {
            const int kk = c16 * 16;
            uint32_t ah[4];
            {
                const float* t0 = sacc[2*c16];
                const float* t1 = sacc[2*c16 + 1];
                ah[0] = packh(t0[0], t0[1]);
                ah[1] = packh(t0[2], t0[3]);
                ah[2] = packh(t1[0], t1[1]);
                ah[3] = packh(t1[2], t1[3]);
            }
            uint32_t bh[8][2];
            #pragma unroll
            for (int np = 0; np < 4; np++) {
                int rv = kk + (lane & 7) + ((lane >> 3) & 1) * 8;
                int cv = np * 16 + (lane >> 4) * 8;
                uint32_t r0, r1, r2, r3;
                ldsm4t(smem_u32(Vf + rv * APITCH + cv), r0, r1, r2, r3);
                bh[2*np][0]=r0; bh[2*np][1]=r1; bh[2*np+1][0]=r2; bh[2*np+1][1]=r3;
            }
            #pragma unroll
            for (int nt = 0; nt < 8; nt++)
                mma_f16(oacc[nt], ah, bh[nt]);
        }
    }

    // reduce row sums across the quad
    d0 += __shfl_xor_sync(0xffffffffu, d0, 1);
    d0 += __shfl_xor_sync(0xffffffffu, d0, 2);
    d1 += __shfl_xor_sync(0xffffffffu, d1, 1);
    d1 += __shfl_xor_sync(0xffffffffu, d1, 2);
    const float inv0 = 1.0f / d0;
    const float inv1 = 1.0f / d1;

    // normalize + write fp16-split output for the proj GEMM
    const int r0 = wid * 16 + (lane >> 2);
    #pragma unroll
    for (int nt = 0; nt < 8; nt++) {
        int c = nt * 8 + 2 * (lane & 3);
        size_t i0 = (size_t)(b * NN + n0 + r0) * DD + h * HD + c;
        size_t i1 = (size_t)(b * NN + n0 + r0 + 8) * DD + h * HD + c;
        uint32_t hh, ll;
        packsplit_h(oacc[nt][0] * inv0, oacc[nt][1] * inv0, hh, ll);
        *reinterpret_cast<uint32_t*>(g_ao_h + i0) = hh;
        *reinterpret_cast<uint32_t*>(g_ao_l + i0) = ll;
        packsplit_h(oacc[nt][2] * inv1, oacc[nt][3] * inv1, hh, ll);
        *reinterpret_cast<uint32_t*>(g_ao_h + i1) = hh;
        *reinterpret_cast<uint32_t*>(g_ao_l + i1) = ll;
    }
}

// ---------------------------------------------------------------------------
__global__ void finalize_mean(float* out, int out_size)
{
    const int base = BB * NN * DD;
    for (int i = base + threadIdx.x; i < out_size; i += blockDim.x)
        out[i] = 1.0f / (float)KC;
}

// ---------------------------------------------------------------------------
extern "C" void kernel_launch(void* const* d_in, const int* in_sizes, int n_in,
                              void* d_out, int out_size)
{
    const float* x      = (const float*)d_in[0];
    const float* ctx    = (const float*)d_in[1];
    const float* q_w    = (const float*)d_in[2];
    const float* q_b    = (const float*)d_in[3];
    const float* kv_w   = (const float*)d_in[4];
    const float* kv_b   = (const float*)d_in[5];
    const float* proj_w = (const float*)d_in[6];
    const float* proj_b = (const float*)d_in[7];
    float* out = (float*)d_out;

    __half *xh, *xl, *qwf, *kvwf, *pwf;
    cudaGetSymbolAddress((void**)&xh,   g_x_h);
    cudaGetSymbolAddress((void**)&xl,   g_x_l);
    cudaGetSymbolAddress((void**)&qwf,  g_qw_f);
    cudaGetSymbolAddress((void**)&kvwf, g_kvw_f);
    cudaGetSymbolAddress((void**)&pwf,  g_pw_f);

    cudaFuncSetAttribute(mmgemm_qkv,  cudaFuncAttributeMaxDynamicSharedMemorySize, GEMM_SMEM);
    cudaFuncSetAttribute(mmgemm_proj, cudaFuncAttributeMaxDynamicSharedMemorySize, GEMM_SMEM);
    cudaFuncSetAttribute(attn_mma,    cudaFuncAttributeMaxDynamicSharedMemorySize, ATTN_SMEM);

    split16_kernel<<<(BB*NN*DD/4 + 255)/256, 256>>>(x, xh, xl, BB*NN*DD);
    conv16_kernel<<<(DD*DD/4 + 255)/256, 256>>>(q_w, qwf, DD*DD);
    conv16_kernel<<<(DD*2*DD/4 + 255)/256, 256>>>(kv_w, kvwf, DD*2*DD);
    conv16_kernel<<<(DD*DD/4 + 255)/256, 256>>>(proj_w, pwf, DD*DD);

    rmsnorm_split<<<BB*KC, 256>>>(ctx);

    // q (fp16, pre-scaled) + kv (fp16) merged
    mmgemm_qkv<<<dim3(24, BB*NN/GBM), 256, GEMM_SMEM>>>(q_b, kv_b);

    // attention (fully single-fp16)
    attn_mma<<<dim3(BB*HH, NN/ANT), 256, ATTN_SMEM>>>();

    // out = attn @ proj_w + proj_b (fp16 2-term, fp32 out)
    mmgemm_proj<<<dim3(DD/GBN, BB*NN/GBM), 256, GEMM_SMEM>>>(proj_b, out);

    if (out_size > BB * NN * DD)
        finalize_mean<<<1, 32>>>(out, out_size);
}